// round 14
// baseline (speedup 1.0000x reference)
#include <cuda_runtime.h>
#include <math.h>

// ---------------- problem constants ----------------
// B=16, L=4 levels (all 32x32), C=256, EMB=64, Lq=4096, HEADS=8, PTS=8, DH=8
// conv: 320ch -> 256ch, 3x3 pad1 on grids 16/32/64/128

// ---------------- device scratch ----------------
__device__ float g_lat  [16777216];   // [l*16+b][256][1024]
__device__ float g_src  [4194304];    // [b][64][4096]
__device__ float g_pos  [262144];     // [64][4096]
__device__ float g_value[4194304];    // [b][4096][64]
__device__ float g_off  [67108864];   // [b][4096][1024]
__device__ float g_attw [16777216];   // [b][4096][256]
__device__ float g_attn [4194304];    // [b][64][4096]
__device__ float g_src2 [4194304];    // [b][64][4096]
__device__ float g_wF   [2949120];    // conv weights tf32 frag order [l][chunk40][mg16][tap9][lane32][4]
__device__ float g_latF [262144];     // lat weights tf32 A-frag [l][kt8 32][mt 16][lane32][4]
__device__ float g_projF[65536];      // proj weights tf32 A-frag [l][kt8 32][mt 4][lane32][4]
__device__ float g_outF [4096];       // out weights tf32 A-frag [kt8 8][mt 4][lane32][4]
__device__ float g_oaF  [90112];      // off(128)+attw(32)+val(8)+spare(8) nt=176 tf32 B-frag [kt8 8][nt 176][lane32][2]
__device__ float g_nfr  [118947840];  // padded resized nf (tf32): [b][320][oh+2][ow+4]

__device__ __forceinline__ unsigned f2tf32(float v) {
    unsigned o;
    asm("cvt.rna.tf32.f32 %0, %1;" : "=r"(o) : "f"(v));
    return o;
}
__device__ __forceinline__ float tf32f(float v) { return __uint_as_float(f2tf32(v)); }

__device__ __forceinline__ void mma_tf32(float* c, uint4 a, unsigned b0, unsigned b1) {
    asm volatile("mma.sync.aligned.m16n8k8.row.col.f32.tf32.tf32.f32 "
        "{%0,%1,%2,%3}, {%4,%5,%6,%7}, {%8,%9}, {%0,%1,%2,%3};\n"
        : "+f"(c[0]), "+f"(c[1]), "+f"(c[2]), "+f"(c[3])
        : "r"(a.x), "r"(a.y), "r"(a.z), "r"(a.w), "r"(b0), "r"(b1));
}
__device__ __forceinline__ void cp16(void* dst, const void* src) {
    unsigned d = (unsigned)__cvta_generic_to_shared(dst);
    asm volatile("cp.async.cg.shared.global [%0], [%1], 16;\n" :: "r"(d), "l"(src));
}
__device__ __forceinline__ void cp_commit() { asm volatile("cp.async.commit_group;\n"); }

// ---------------- conv weight repack: fragment-order + tf32 ----------------
__global__ void k_wtrans(const float* __restrict__ w) {
    int idx = blockIdx.x * 256 + threadIdx.x;
    if (idx >= 4 * 40 * 16 * 9 * 32 * 4) return;
    int r    = idx & 3;
    int lane = (idx >> 2) & 31;
    int tap  = (idx >> 7) % 9;
    int mg   = (idx / 1152) & 15;
    int chunk= (idx / 18432) % 40;
    int l    = idx / 737280;
    int oc   = mg * 16 + (lane >> 2) + 8 * (r & 1);
    int ic   = chunk * 8 + (lane & 3) + 4 * (r >> 1);
    float v = w[(((size_t)(l * 256 + oc)) * 320 + ic) * 9 + tap];
    g_wF[idx] = tf32f(v);
}

// ---------------- merged prep: lat/proj/out A packs, off+attw+val B pack, pos ----------------
__global__ void k_prep(const float* __restrict__ lat_w, const float* __restrict__ proj_w,
                       const float* __restrict__ off_w, const float* __restrict__ attw_w,
                       const float* __restrict__ val_w, const float* __restrict__ out_w,
                       const float* __restrict__ lemb) {
    int idx = blockIdx.x * 256 + threadIdx.x;
    if (idx < 262144) {                 // lateral A-frag pack
        int r = idx & 3, lane = (idx >> 2) & 31, mt = (idx >> 7) & 15;
        int kt8 = (idx >> 11) & 31, l = idx >> 16;
        int row = mt * 16 + (lane >> 2) + 8 * (r & 1);
        int k   = kt8 * 8 + (lane & 3) + 4 * (r >> 1);
        g_latF[idx] = tf32f(lat_w[(size_t)l * 65536 + row * 256 + k]);
    } else if (idx < 327680) {          // proj A-frag pack
        int id = idx - 262144;
        int r = id & 3, lane = (id >> 2) & 31, mt = (id >> 7) & 3;
        int kt8 = (id >> 9) & 31, l = id >> 14;
        int row = mt * 16 + (lane >> 2) + 8 * (r & 1);
        int k   = kt8 * 8 + (lane & 3) + 4 * (r >> 1);
        g_projF[id] = tf32f(proj_w[(size_t)l * 16384 + row * 256 + k]);
    } else if (idx < 417792) {          // off+attw+val B-frag pack (nt 0..175)
        int id = idx - 327680;
        int i = id & 1, lane = (id >> 1) & 31, nt = (id >> 6) % 176, kt8 = id / 11264;
        int n = nt * 8 + (lane >> 2);
        int k = kt8 * 8 + (lane & 3) + 4 * i;
        float v;
        if (n < 1024)       v = off_w[n * 64 + k];
        else if (n < 1280)  v = attw_w[(n - 1024) * 64 + k];
        else if (n < 1344)  v = val_w[(n - 1280) * 64 + k];
        else                v = 0.f;
        g_oaF[id] = tf32f(v);
    } else if (idx < 679936) {          // sine pos + level embed
        int id = idx - 417792;
        int e = id >> 12, q = id & 4095;
        int l = q >> 10, hw = q & 1023, y = hw >> 5, x = hw & 31;
        int e2 = (e < 32) ? e : (e - 32);
        int n  = (e < 32) ? (y + 1) : (x + 1);
        int j  = e2 >> 1;
        float t = powf(10000.f, (float)j * (1.f / 16.f));
        float p = (float)n / t;
        float v = (e2 & 1) ? cosf(p) : sinf(p);
        g_pos[id] = v + lemb[l * 64 + e];
    } else if (idx < 684032) {          // out-proj A-frag pack (4096 entries)
        int id = idx - 679936;
        int r = id & 3, lane = (id >> 2) & 31, mt = (id >> 7) & 3, kt8 = id >> 9;
        int row = mt * 16 + (lane >> 2) + 8 * (r & 1);
        int k   = kt8 * 8 + (lane & 3) + 4 * (r >> 1);
        g_outF[id] = tf32f(out_w[row * 64 + k]);
    }
}

// ---------------- lateral 1x1 conv via TF32 MMA: M=256 K=256 N=1024 per (l,b) ----------------
__global__ __launch_bounds__(256) void k_lat_tc(
    const float* __restrict__ x0, const float* __restrict__ x1,
    const float* __restrict__ x2, const float* __restrict__ x3,
    const float* __restrict__ bias)
{
    __shared__ __align__(16) float AsF[2048];
    __shared__ __align__(16) float Bs[32 * 68];
    int lb = blockIdx.z, l = lb >> 4, b = lb & 15;
    const float* X = (l == 0 ? x0 : l == 1 ? x1 : l == 2 ? x2 : x3) + (size_t)b * 262144;
    const float* AF = g_latF + (size_t)l * 65536;
    int m0 = blockIdx.y * 64, n0 = blockIdx.x * 64;
    int tid = threadIdx.x, lane = tid & 31, w = tid >> 5;
    int warp_m = w >> 2, warp_n = w & 3;
    int n_w = warp_n * 16;
    float acc[2][2][4] = {};
    for (int c = 0; c < 8; c++) {
        int k0 = c * 32;
        __syncthreads();
#pragma unroll
        for (int i = 0; i < 2; i++) {
            int id = tid + i * 256;
            int kt = id >> 7, rem = id & 127;
            ((float4*)AsF)[id] =
                ((const float4*)AF)[((k0 >> 3) + kt) * 512 + (m0 >> 4) * 32 + rem];
        }
#pragma unroll
        for (int i = 0; i < 2; i++) {
            int id = tid + i * 256;
            int k = id >> 4, n4 = (id & 15) << 2;
            float4 v = *(const float4*)&X[(size_t)(k0 + k) * 1024 + n0 + n4];
            v.x = tf32f(v.x); v.y = tf32f(v.y); v.z = tf32f(v.z); v.w = tf32f(v.w);
            *(float4*)&Bs[k * 68 + n4] = v;
        }
        __syncthreads();
#pragma unroll
        for (int kk = 0; kk < 4; kk++) {
            uint4 A0 = *(const uint4*)&AsF[(kk * 4 + warp_m * 2 + 0) * 128 + lane * 4];
            uint4 A1 = *(const uint4*)&AsF[(kk * 4 + warp_m * 2 + 1) * 128 + lane * 4];
#pragma unroll
            for (int j = 0; j < 2; j++) {
                const float* bp = &Bs[(kk * 8 + (lane & 3)) * 68 + n_w + j * 8 + (lane >> 2)];
                unsigned b0 = __float_as_uint(bp[0]);
                unsigned b1 = __float_as_uint(bp[4 * 68]);
                mma_tf32(acc[0][j], A0, b0, b1);
                mma_tf32(acc[1][j], A1, b0, b1);
            }
        }
    }
    float* O = g_lat + (size_t)lb * 262144;
    int row_l = lane >> 2, colp = (lane & 3) << 1;
#pragma unroll
    for (int h = 0; h < 2; h++)
#pragma unroll
        for (int j = 0; j < 2; j++) {
            int row = m0 + warp_m * 32 + h * 16 + row_l;
            int col = n0 + n_w + j * 8 + colp;
            float b0v = bias[l * 256 + row], b1v = bias[l * 256 + row + 8];
            *(float2*)&O[(size_t)row * 1024 + col] =
                make_float2(acc[h][j][0] + b0v, acc[h][j][1] + b0v);
            *(float2*)&O[(size_t)(row + 8) * 1024 + col] =
                make_float2(acc[h][j][2] + b1v, acc[h][j][3] + b1v);
        }
}

// ---------------- proj (256->64) via TF32 MMA + BN + ReLU -> g_src ----------------
__global__ __launch_bounds__(256) void k_proj_tc(
    const float* __restrict__ bias,
    const float* __restrict__ bng, const float* __restrict__ bnb,
    const float* __restrict__ bnm, const float* __restrict__ bnv)
{
    __shared__ __align__(16) float AsF[2048];
    __shared__ __align__(16) float Bs[32 * 68];
    int lb = blockIdx.z, l = lb >> 4, b = lb & 15;
    const float* X = g_lat + (size_t)lb * 262144;
    const float* AF = g_projF + (size_t)l * 16384;
    int n0 = blockIdx.x * 64;
    int tid = threadIdx.x, lane = tid & 31, w = tid >> 5;
    int warp_m = w >> 2, warp_n = w & 3;
    int n_w = warp_n * 16;
    float acc[2][2][4] = {};
    for (int c = 0; c < 8; c++) {
        int k0 = c * 32;
        __syncthreads();
        {
            int id = tid;
#pragma unroll
            for (int i = 0; i < 2; i++, id += 256) {
                int kt = id >> 7, rem = id & 127;
                ((float4*)AsF)[id] = ((const float4*)AF)[((c * 4 + kt) * 128) + rem];
            }
        }
#pragma unroll
        for (int i = 0; i < 2; i++) {
            int id = tid + i * 256;
            int k = id >> 4, n4 = (id & 15) << 2;
            float4 v = *(const float4*)&X[(size_t)(k0 + k) * 1024 + n0 + n4];
            v.x = tf32f(v.x); v.y = tf32f(v.y); v.z = tf32f(v.z); v.w = tf32f(v.w);
            *(float4*)&Bs[k * 68 + n4] = v;
        }
        __syncthreads();
#pragma unroll
        for (int kk = 0; kk < 4; kk++) {
            uint4 A0 = *(const uint4*)&AsF[(kk * 4 + warp_m * 2 + 0) * 128 + lane * 4];
            uint4 A1 = *(const uint4*)&AsF[(kk * 4 + warp_m * 2 + 1) * 128 + lane * 4];
#pragma unroll
            for (int j = 0; j < 2; j++) {
                const float* bp = &Bs[(kk * 8 + (lane & 3)) * 68 + n_w + j * 8 + (lane >> 2)];
                unsigned b0 = __float_as_uint(bp[0]);
                unsigned b1 = __float_as_uint(bp[4 * 68]);
                mma_tf32(acc[0][j], A0, b0, b1);
                mma_tf32(acc[1][j], A1, b0, b1);
            }
        }
    }
    int row_l = lane >> 2, colp = (lane & 3) << 1;
#pragma unroll
    for (int h = 0; h < 2; h++) {
        int m = warp_m * 32 + h * 16 + row_l;
        float sc0 = bng[l * 64 + m] * rsqrtf(bnv[l * 64 + m] + 1e-5f);
        float sh0 = bnb[l * 64 + m] - bnm[l * 64 + m] * sc0 + bias[l * 64 + m] * sc0;
        float sc1 = bng[l * 64 + m + 8] * rsqrtf(bnv[l * 64 + m + 8] + 1e-5f);
        float sh1 = bnb[l * 64 + m + 8] - bnm[l * 64 + m + 8] * sc1 + bias[l * 64 + m + 8] * sc1;
#pragma unroll
        for (int j = 0; j < 2; j++) {
            int col = n0 + n_w + j * 8 + colp;
            float* p0 = &g_src[((size_t)b * 64 + m) * 4096 + l * 1024 + col];
            float* p1 = &g_src[((size_t)b * 64 + m + 8) * 4096 + l * 1024 + col];
            *(float2*)p0 = make_float2(fmaxf(acc[h][j][0] * sc0 + sh0, 0.f),
                                       fmaxf(acc[h][j][1] * sc0 + sh0, 0.f));
            *(float2*)p1 = make_float2(fmaxf(acc[h][j][2] * sc1 + sh1, 0.f),
                                       fmaxf(acc[h][j][3] * sc1 + sh1, 0.f));
        }
    }
}

// ---------------- off(1024)+attw(256) GEMM via TF32 MMA: M=q4096, N=1280, K=64 ----------------
__global__ __launch_bounds__(256) void k_off_tc(const float* __restrict__ off_b,
                                                const float* __restrict__ attw_b)
{
    __shared__ __align__(16) float As[64 * 68];
    __shared__ __align__(16) float BsF[4096];
    int b = blockIdx.z;
    int q0 = blockIdx.y * 64, n0 = blockIdx.x * 64;
    int tid = threadIdx.x, lane = tid & 31, w = tid >> 5;
    int warp_m = w >> 2, warp_n = w & 3;
    const float* S = g_src + (size_t)b * 262144;
#pragma unroll
    for (int i = 0; i < 4; i++) {
        int id = tid + i * 256;
        int k = id >> 4, q4 = (id & 15) << 2;
        float4 v = *(const float4*)&S[(size_t)k * 4096 + q0 + q4];
        float4 p = *(const float4*)&g_pos[(size_t)k * 4096 + q0 + q4];
        v.x = tf32f(v.x + p.x); v.y = tf32f(v.y + p.y);
        v.z = tf32f(v.z + p.z); v.w = tf32f(v.w + p.w);
        *(float4*)&As[k * 68 + q4] = v;
    }
#pragma unroll
    for (int i = 0; i < 4; i++) {
        int id = tid + i * 256;
        int kt8 = id >> 7, rem = id & 127;
        ((float4*)BsF)[id] = ((const float4*)g_oaF)[(kt8 * 176 + (n0 >> 3)) * 16 + rem];
    }
    __syncthreads();
    float acc[2][2][4] = {};
#pragma unroll
    for (int kk8 = 0; kk8 < 8; kk8++) {
        uint4 A[2];
#pragma unroll
        for (int h = 0; h < 2; h++) {
            const float* ap = &As[(kk8 * 8 + (lane & 3)) * 68 + warp_m * 32 + h * 16 + (lane >> 2)];
            A[h].x = __float_as_uint(ap[0]);
            A[h].y = __float_as_uint(ap[8]);
            A[h].z = __float_as_uint(ap[4 * 68]);
            A[h].w = __float_as_uint(ap[4 * 68 + 8]);
        }
#pragma unroll
        for (int j = 0; j < 2; j++) {
            float2 bv = *(const float2*)&BsF[(kk8 * 8 + warp_n * 2 + j) * 64 + lane * 2];
            unsigned b0 = __float_as_uint(bv.x), b1 = __float_as_uint(bv.y);
            mma_tf32(acc[0][j], A[0], b0, b1);
            mma_tf32(acc[1][j], A[1], b0, b1);
        }
    }
    int row_l = lane >> 2, colp = (lane & 3) << 1;
    bool is_off = (n0 < 1024);
#pragma unroll
    for (int h = 0; h < 2; h++)
#pragma unroll
        for (int j = 0; j < 2; j++) {
            int q = q0 + warp_m * 32 + h * 16 + row_l;
            int col = n0 + warp_n * 16 + j * 8 + colp;
            if (is_off) {
                float bb0 = off_b[col], bb1 = off_b[col + 1];
                float* op = g_off + ((size_t)b * 4096 + q) * 1024 + col;
                *(float2*)op = make_float2(acc[h][j][0] + bb0, acc[h][j][1] + bb1);
                *(float2*)(op + 8 * 1024) = make_float2(acc[h][j][2] + bb0, acc[h][j][3] + bb1);
            } else {
                int ca = col - 1024;
                float bb0 = attw_b[ca], bb1 = attw_b[ca + 1];
                float* op = g_attw + ((size_t)b * 4096 + q) * 256 + ca;
                *(float2*)op = make_float2(acc[h][j][0] + bb0, acc[h][j][1] + bb1);
                *(float2*)(op + 8 * 256) = make_float2(acc[h][j][2] + bb0, acc[h][j][3] + bb1);
            }
        }
}

// ---------------- value GEMM via TF32 MMA: M=q4096, N=64, K=64 -> g_value [b][q][64] ----------------
__global__ __launch_bounds__(256) void k_val_tc(const float* __restrict__ bias)
{
    __shared__ __align__(16) float As[64 * 68];
    __shared__ __align__(16) float BsF[4096];
    int b = blockIdx.z;
    int q0 = blockIdx.y * 64;
    int tid = threadIdx.x, lane = tid & 31, w = tid >> 5;
    int warp_m = w >> 2, warp_n = w & 3;
    const float* S = g_src + (size_t)b * 262144;
#pragma unroll
    for (int i = 0; i < 4; i++) {
        int id = tid + i * 256;
        int k = id >> 4, q4 = (id & 15) << 2;
        float4 v = *(const float4*)&S[(size_t)k * 4096 + q0 + q4];
        v.x = tf32f(v.x); v.y = tf32f(v.y); v.z = tf32f(v.z); v.w = tf32f(v.w);
        *(float4*)&As[k * 68 + q4] = v;
    }
#pragma unroll
    for (int i = 0; i < 4; i++) {
        int id = tid + i * 256;
        int kt8 = id >> 7, rem = id & 127;
        ((float4*)BsF)[id] = ((const float4*)g_oaF)[(kt8 * 176 + 160 + (rem >> 4)) * 16 + (rem & 15)];
    }
    __syncthreads();
    float acc[2][2][4] = {};
#pragma unroll
    for (int kk8 = 0; kk8 < 8; kk8++) {
        uint4 A[2];
#pragma unroll
        for (int h = 0; h < 2; h++) {
            const float* ap = &As[(kk8 * 8 + (lane & 3)) * 68 + warp_m * 32 + h * 16 + (lane >> 2)];
            A[h].x = __float_as_uint(ap[0]);
            A[h].y = __float_as_uint(ap[8]);
            A[h].z = __float_as_uint(ap[4 * 68]);
            A[h].w = __float_as_uint(ap[4 * 68 + 8]);
        }
#pragma unroll
        for (int j = 0; j < 2; j++) {
            float2 bv = *(const float2*)&BsF[(kk8 * 8 + warp_n * 2 + j) * 64 + lane * 2];
            unsigned b0 = __float_as_uint(bv.x), b1 = __float_as_uint(bv.y);
            mma_tf32(acc[0][j], A[0], b0, b1);
            mma_tf32(acc[1][j], A[1], b0, b1);
        }
    }
    int row_l = lane >> 2, colp = (lane & 3) << 1;
#pragma unroll
    for (int h = 0; h < 2; h++)
#pragma unroll
        for (int j = 0; j < 2; j++) {
            int q = q0 + warp_m * 32 + h * 16 + row_l;
            int col = warp_n * 16 + j * 8 + colp;
            float bb0 = bias[col], bb1 = bias[col + 1];
            float* op = g_value + ((size_t)b * 4096 + q) * 64 + col;
            *(float2*)op = make_float2(acc[h][j][0] + bb0, acc[h][j][1] + bb1);
            *(float2*)(op + 8 * 64) = make_float2(acc[h][j][2] + bb0, acc[h][j][3] + bb1);
        }
}

// ---------------- out-proj via TF32 MMA (lat-style): M=64, K=64, N=4096 per b ----------------
__global__ __launch_bounds__(256) void k_out_tc(const float* __restrict__ bias)
{
    __shared__ __align__(16) float AsF[2048];
    __shared__ __align__(16) float Bs[32 * 68];
    int b = blockIdx.z;
    const float* X = g_attn + (size_t)b * 262144;
    int n0 = blockIdx.x * 64;
    int tid = threadIdx.x, lane = tid & 31, w = tid >> 5;
    int warp_m = w >> 2, warp_n = w & 3;
    int n_w = warp_n * 16;
    float acc[2][2][4] = {};
    for (int c = 0; c < 2; c++) {
        int k0 = c * 32;
        __syncthreads();
#pragma unroll
        for (int i = 0; i < 2; i++) {
            int id = tid + i * 256;
            int kt = id >> 7, rem = id & 127;
            ((float4*)AsF)[id] = ((const float4*)g_outF)[((k0 >> 3) + kt) * 128 + rem];
        }
#pragma unroll
        for (int i = 0; i < 2; i++) {
            int id = tid + i * 256;
            int k = id >> 4, n4 = (id & 15) << 2;
            float4 v = *(const float4*)&X[(size_t)(k0 + k) * 4096 + n0 + n4];
            v.x = tf32f(v.x); v.y = tf32f(v.y); v.z = tf32f(v.z); v.w = tf32f(v.w);
            *(float4*)&Bs[k * 68 + n4] = v;
        }
        __syncthreads();
#pragma unroll
        for (int kk = 0; kk < 4; kk++) {
            uint4 A0 = *(const uint4*)&AsF[(kk * 4 + warp_m * 2 + 0) * 128 + lane * 4];
            uint4 A1 = *(const uint4*)&AsF[(kk * 4 + warp_m * 2 + 1) * 128 + lane * 4];
#pragma unroll
            for (int j = 0; j < 2; j++) {
                const float* bp = &Bs[(kk * 8 + (lane & 3)) * 68 + n_w + j * 8 + (lane >> 2)];
                unsigned b0 = __float_as_uint(bp[0]);
                unsigned b1 = __float_as_uint(bp[4 * 68]);
                mma_tf32(acc[0][j], A0, b0, b1);
                mma_tf32(acc[1][j], A1, b0, b1);
            }
        }
    }
    float* O = g_src2 + (size_t)b * 262144;
    int row_l = lane >> 2, colp = (lane & 3) << 1;
#pragma unroll
    for (int h = 0; h < 2; h++)
#pragma unroll
        for (int j = 0; j < 2; j++) {
            int row = warp_m * 32 + h * 16 + row_l;
            int col = n0 + n_w + j * 8 + colp;
            float b0v = bias[row], b1v = bias[row + 8];
            *(float2*)&O[(size_t)row * 4096 + col] =
                make_float2(acc[h][j][0] + b0v, acc[h][j][1] + b0v);
            *(float2*)&O[(size_t)(row + 8) * 4096 + col] =
                make_float2(acc[h][j][2] + b1v, acc[h][j][3] + b1v);
        }
}

// ---------------- deformable attention sampling ----------------
__global__ void k_sample() {
    int idx = blockIdx.x * 256 + threadIdx.x;
    if (idx >= 16 * 4096 * 8) return;
    int h = idx & 7, q = (idx >> 3) & 4095, b = idx >> 15;
    const float* aw  = g_attw + (size_t)(b * 4096 + q) * 256 + h * 32;
    const float* off = g_off  + (size_t)(b * 4096 + q) * 1024 + h * 64;
    float lg[32];
#pragma unroll
    for (int j = 0; j < 32; j++) lg[j] = aw[j];
    float mx = lg[0];
#pragma unroll
    for (int j = 1; j < 32; j++) mx = fmaxf(mx, lg[j]);
    float s = 0.f;
#pragma unroll
    for (int j = 0; j < 32; j++) { lg[j] = __expf(lg[j] - mx); s += lg[j]; }
    float inv = 1.f / s;
    int y = (q & 1023) >> 5, x = q & 31;
    float rx = (x + 0.5f) * (1.f / 32.f), ry = (y + 0.5f) * (1.f / 32.f);
    float acc[8] = {0, 0, 0, 0, 0, 0, 0, 0};
    const float* vb = g_value + (size_t)b * 4096 * 64 + h * 8;

#define SAMP(XX, YY, WW2) do { int xx = (XX), yy = (YY);                            \
        if (xx >= 0 && xx < 32 && yy >= 0 && yy < 32) {                             \
            const float4* rp = (const float4*)(vl + (size_t)(yy * 32 + xx) * 64);   \
            float4 a = rp[0], c = rp[1]; float wv = (WW2);                          \
            acc[0] += wv * a.x; acc[1] += wv * a.y; acc[2] += wv * a.z; acc[3] += wv * a.w; \
            acc[4] += wv * c.x; acc[5] += wv * c.y; acc[6] += wv * c.z; acc[7] += wv * c.w; } } while (0)

#pragma unroll
    for (int l = 0; l < 4; l++) {
        const float* vl = vb + (size_t)l * 1024 * 64;
#pragma unroll
        for (int p = 0; p < 8; p++) {
            float wgt = lg[l * 8 + p] * inv;
            float fx = (rx + off[l * 16 + p * 2 + 0] * (1.f / 32.f)) * 32.f - 0.5f;
            float fy = (ry + off[l * 16 + p * 2 + 1] * (1.f / 32.f)) * 32.f - 0.5f;
            float x0f = floorf(fx), y0f = floorf(fy);
            int xi = (int)x0f, yi = (int)y0f;
            float wx = fx - x0f, wy = fy - y0f;
            SAMP(xi,     yi,     wgt * (1.f - wx) * (1.f - wy));
            SAMP(xi + 1, yi,     wgt * wx * (1.f - wy));
            SAMP(xi,     yi + 1, wgt * (1.f - wx) * wy);
            SAMP(xi + 1, yi + 1, wgt * wx * wy);
        }
    }
#undef SAMP
#pragma unroll
    for (int d = 0; d < 8; d++)
        g_attn[((size_t)b * 64 + h * 8 + d) * 4096 + q] = acc[d];
}

// ---------------- fuse + bilinear resize -> padded g_nfr (tf32, zero halo) ----------------
__global__ void k_fuse_resize(int l, int oh, int ow, int PH, int PW4,
                              float hs, size_t nfr_off, int count) {
    int idx = blockIdx.x * 256 + threadIdx.x;
    if (idx >= count) return;
    int px = idx % PW4;
    int t = idx / PW4;
    int py = t % PH; t /= PH;
    int c = t % 320;
    int b = t / 320;
    int gy = py - 1, gx = px - 1;
    float res = 0.f;
    if (gy >= 0 && gy < oh && gx >= 0 && gx < ow) {
        float sy = fmaxf((gy + 0.5f) * hs - 0.5f, 0.f);
        float sx = fmaxf((gx + 0.5f) * hs - 0.5f, 0.f);
        int y0 = (int)sy, x0 = (int)sx;
        float fy = sy - y0, fx = sx - x0;
        int y1 = min(y0 + 1, 31), x1 = min(x0 + 1, 31);
        const float* p;
        if (c < 256)
            p = g_lat + ((size_t)(l * 16 + b) * 256 + c) * 1024;
        else
            p = g_src2 + ((size_t)b * 64 + (c - 256)) * 4096 + l * 1024;
        float v00 = p[y0 * 32 + x0], v01 = p[y0 * 32 + x1];
        float v10 = p[y1 * 32 + x0], v11 = p[y1 * 32 + x1];
        float r0 = v00 * (1.f - fy) + v10 * fy;
        float r1 = v01 * (1.f - fy) + v11 * fy;
        res = tf32f(r0 * (1.f - fx) + r1 * fx);
    }
    g_nfr[nfr_off + (size_t)idx] = res;
}

// ---------------- 3x3 conv 320->256 pad1, TF32 MMA, 64oc, shared-B, 3-stage cp.async ring ----------------
// Block: 64 oc x 16x16 px; 8 warps; warp = ALL 64 oc x (rows 2w,2w+1) x 16 px.
// 3-stage ring -> ONE __syncthreads per chunk; stage c+2 targets buffer (c-1)%3
// (free after this iteration's barrier). Dynamic smem: 3 x (4608+2880) x 4 = 89856 B.
__global__ __launch_bounds__(256) void k_conv_tc(int l, int oh, int ow, int PW4, int planesz,
                                                 size_t nfr_off,
                                                 const float* __restrict__ cb,
                                                 float* __restrict__ out, size_t out_off)
{
    extern __shared__ __align__(16) float smem[];
    float* Ws = smem;                  // 3 x 4608 floats
    float* Is = smem + 13824;          // 3 x 2880 floats
    int b = blockIdx.z;
    int ocb = blockIdx.y;              // 0..3 -> 64 oc
    int tiles_x = ow >> 4;
    int py0 = (blockIdx.x / tiles_x) << 4;
    int px0 = (blockIdx.x % tiles_x) << 4;
    int tid = threadIdx.x;
    int lane = tid & 31, w = tid >> 5;
    int r0 = w * 2;
    int ohow = oh * ow;
    const float4* wsrc = (const float4*)g_wF
                       + (size_t)l * 184320 + (size_t)ocb * 1152;
    const float* ibase = g_nfr + nfr_off + (size_t)b * 320 * planesz;
    float acc[4][4][4] = {};

    // per-thread input staging ops (loop-invariant, <=3 entries — registers)
    int nops = 0;
    int s_off[3];
    int g_ofs[3];
#pragma unroll
    for (int i = tid; i < 720; i += 256) {
        int kc = i / 90, r2 = i - kc * 90;
        int iy = r2 / 5, s = r2 - iy * 5;
        s_off[nops] = kc * 360 + iy * 20 + s * 4;
        g_ofs[nops] = kc * planesz + (py0 + iy) * PW4 + px0 + s * 4;
        nops++;
    }

#define ISSUE_STAGE(stage, buf) do {                                           \
        const float* chb = ibase + (size_t)((stage) * 8) * planesz;            \
        float* isb_ = Is + (buf) * 2880;                                       \
        for (int j2 = 0; j2 < nops; j2++) cp16(isb_ + s_off[j2], chb + g_ofs[j2]); \
        const float4* wc = wsrc + (size_t)(stage) * 4608;                      \
        float4* wd = (float4*)(Ws + (buf) * 4608);                             \
        _Pragma("unroll")                                                      \
        for (int i2 = 0; i2 < 5; i2++) {                                       \
            int k = tid + i2 * 256;                                            \
            if (k < 1152) cp16(&wd[k], &wc[k]);                                \
        }                                                                      \
        cp_commit(); } while (0)

    ISSUE_STAGE(0, 0);
    ISSUE_STAGE(1, 1);

    int buf = 0;
    for (int c = 0; c < 40; c++) {
        if (c < 39) { asm volatile("cp.async.wait_group 1;\n"); }
        else        { asm volatile("cp.async.wait_group 0;\n"); }
        __syncthreads();                 // all warps done with chunk c-1: buffer (c-1)%3 free
        if (c + 2 < 40) {
            int tbuf = buf + 2; if (tbuf >= 3) tbuf -= 3;
            ISSUE_STAGE(c + 2, tbuf);
        }
        const float* wsA = Ws + buf * 4608 + lane * 4;
        const float* isb = Is + buf * 2880 + (lane & 3) * 360 + (lane >> 2);
#pragma unroll
        for (int tap = 0; tap < 9; tap++) {
            int dy = tap / 3, dx = tap - dy * 3;
            uint4 A0 = *(const uint4*)(wsA + tap * 128);
            uint4 A1 = *(const uint4*)(wsA + 1152 + tap * 128);
            uint4 A2 = *(const uint4*)(wsA + 2304 + tap * 128);
            uint4 A3 = *(const uint4*)(wsA + 3456 + tap * 128);
            const float* ib = isb + (r0 + dy) * 20 + dx;
#pragma unroll
            for (int j = 0; j < 4; j++) {
                const float* bp = ib + (j >> 1) * 20 + ((j & 1) << 3);
                unsigned b0 = __float_as_uint(bp[0]);
                unsigned b1 = __float_as_uint(bp[4 * 360]);
                mma_tf32(acc[0][j], A0, b0, b1);
                mma_tf32(acc[1][j], A1, b0, b1);
                mma_tf32(acc[2][j], A2, b0, b1);
                mma_tf32(acc[3][j], A3, b0, b1);
            }
        }
        buf++; if (buf >= 3) buf = 0;
    }
#undef ISSUE_STAGE

    // epilogue
    int row = lane >> 2, colp = (lane & 3) << 1;
    int oc0 = ocb * 64;
#pragma unroll
    for (int m = 0; m < 4; m++) {
        int ocA = oc0 + m * 16 + row;
        float bA = cb[l * 256 + ocA];
        float bB = cb[l * 256 + ocA + 8];
        float* outA = out + out_off + (size_t)(b * 256 + ocA) * ohow;
        float* outB = outA + (size_t)8 * ohow;
#pragma unroll
        for (int j = 0; j < 4; j++) {
            int gy = py0 + r0 + (j >> 1);
            int gx = px0 + ((j & 1) << 3) + colp;
            float2 v0 = make_float2(acc[m][j][0] + bA, acc[m][j][1] + bA);
            float2 v1 = make_float2(acc[m][j][2] + bB, acc[m][j][3] + bB);
            *(float2*)(outA + gy * ow + gx) = v0;
            *(float2*)(outB + gy * ow + gx) = v1;
        }
    }
}

// ---------------- launch ----------------
extern "C" void kernel_launch(void* const* d_in, const int* in_sizes, int n_in,
                              void* d_out, int out_size)
{
    const float* x0     = (const float*)d_in[0];
    const float* x1     = (const float*)d_in[1];
    const float* x2     = (const float*)d_in[2];
    const float* x3     = (const float*)d_in[3];
    const float* lat_w  = (const float*)d_in[4];
    const float* lat_b  = (const float*)d_in[5];
    const float* proj_w = (const float*)d_in[6];
    const float* proj_b = (const float*)d_in[7];
    const float* bn_g   = (const float*)d_in[8];
    const float* bn_b   = (const float*)d_in[9];
    const float* bn_m   = (const float*)d_in[10];
    const float* bn_v   = (const float*)d_in[11];
    const float* conv_w = (const float*)d_in[12];
    const float* conv_b = (const float*)d_in[13];
    const float* lemb   = (const float*)d_in[14];
    const float* off_w  = (const float*)d_in[15];
    const float* off_b  = (const float*)d_in[16];
    const float* attw_w = (const float*)d_in[17];
    const float* attw_b = (const float*)d_in[18];
    const float* val_w  = (const float*)d_in[19];
    const float* val_b  = (const float*)d_in[20];
    const float* out_w  = (const float*)d_in[21];
    const float* out_b  = (const float*)d_in[22];
    float* out = (float*)d_out;

    // idempotent, unconditional (no static guards): allow 89856 B dynamic smem
    cudaFuncSetAttribute(k_conv_tc, cudaFuncAttributeMaxDynamicSharedMemorySize, 92160);

    k_wtrans<<<11520, 256>>>(conv_w);
    k_prep<<<2672, 256>>>(lat_w, proj_w, off_w, attw_w, val_w, out_w, lemb);
    k_lat_tc<<<dim3(16, 4, 64), 256>>>(x0, x1, x2, x3, lat_b);
    k_proj_tc<<<dim3(16, 1, 64), 256>>>(proj_b, bn_g, bn_b, bn_m, bn_v);
    k_val_tc<<<dim3(1, 64, 16), 256>>>(val_b);
    k_off_tc<<<dim3(20, 64, 16), 256>>>(off_b, attw_b);
    k_sample<<<2048, 256>>>();
    k_out_tc<<<dim3(64, 1, 16), 256>>>(out_b);

    const int    OHS[4]  = {16, 32, 64, 128};
    const int    PW4S[4] = {20, 36, 68, 132};
    const int    PLSZ[4] = {360, 1224, 4488, 17160};
    const size_t NFR[4]  = {0, 1843200, 8110080, 31088640};
    const size_t OUT[4]  = {0, 1048576, 5242880, 22020096};
    for (int l = 0; l < 4; l++) {
        int oh = OHS[l], ow = oh;
        int PH = oh + 2, PW4 = PW4S[l];
        int count = 16 * 320 * PH * PW4;
        float hs = 32.0f / (float)oh;
        k_fuse_resize<<<count / 256, 256>>>(l, oh, ow, PH, PW4, hs, NFR[l], count);
    }
    for (int l = 0; l < 4; l++) {
        int oh = OHS[l], ow = oh;
        dim3 grid((oh / 16) * (ow / 16), 4, 16);
        k_conv_tc<<<grid, 256, 89856>>>(l, oh, ow, PW4S[l], PLSZ[l], NFR[l],
                                        conv_b, out, OUT[l]);
    }
}

// round 15
// speedup vs baseline: 1.0060x; 1.0060x over previous
#include <cuda_runtime.h>
#include <math.h>

// ---------------- problem constants ----------------
// B=16, L=4 levels (all 32x32), C=256, EMB=64, Lq=4096, HEADS=8, PTS=8, DH=8
// conv: 320ch -> 256ch, 3x3 pad1 on grids 16/32/64/128

// ---------------- device scratch ----------------
__device__ float g_lat  [16777216];   // [l*16+b][256][1024]
__device__ float g_src  [4194304];    // [b][64][4096]
__device__ float g_pos  [262144];     // [64][4096]
__device__ float g_value[4194304];    // [b][4096][64]
__device__ float g_off  [67108864];   // [b][4096][1024]
__device__ float g_attw [16777216];   // [b][4096][256]
__device__ float g_attn [4194304];    // [b][64][4096]
__device__ float g_src2 [4194304];    // [b][64][4096]
__device__ float g_wF   [2949120];    // conv weights tf32 frag order [l][chunk40][mg16][tap9][lane32][4]
__device__ float g_latF [262144];     // lat weights tf32 A-frag [l][kt8 32][mt 16][lane32][4]
__device__ float g_projF[65536];      // proj weights tf32 A-frag [l][kt8 32][mt 4][lane32][4]
__device__ float g_outF [4096];       // out weights tf32 A-frag [kt8 8][mt 4][lane32][4]
__device__ float g_oaF  [90112];      // off(128)+attw(32)+val(8)+spare(8) nt=176 tf32 B-frag [kt8 8][nt 176][lane32][2]
__device__ float g_nfr  [118947840];  // padded resized nf (tf32): [b][320][oh+2][ow+4]

__device__ __forceinline__ unsigned f2tf32(float v) {
    unsigned o;
    asm("cvt.rna.tf32.f32 %0, %1;" : "=r"(o) : "f"(v));
    return o;
}
__device__ __forceinline__ float tf32f(float v) { return __uint_as_float(f2tf32(v)); }

__device__ __forceinline__ void mma_tf32(float* c, uint4 a, unsigned b0, unsigned b1) {
    asm volatile("mma.sync.aligned.m16n8k8.row.col.f32.tf32.tf32.f32 "
        "{%0,%1,%2,%3}, {%4,%5,%6,%7}, {%8,%9}, {%0,%1,%2,%3};\n"
        : "+f"(c[0]), "+f"(c[1]), "+f"(c[2]), "+f"(c[3])
        : "r"(a.x), "r"(a.y), "r"(a.z), "r"(a.w), "r"(b0), "r"(b1));
}
__device__ __forceinline__ void cp16(void* dst, const void* src) {
    unsigned d = (unsigned)__cvta_generic_to_shared(dst);
    asm volatile("cp.async.cg.shared.global [%0], [%1], 16;\n" :: "r"(d), "l"(src));
}
__device__ __forceinline__ void cp_commit() { asm volatile("cp.async.commit_group;\n"); }

// ---------------- conv weight repack: fragment-order + tf32 ----------------
__global__ void k_wtrans(const float* __restrict__ w) {
    int idx = blockIdx.x * 256 + threadIdx.x;
    if (idx >= 4 * 40 * 16 * 9 * 32 * 4) return;
    int r    = idx & 3;
    int lane = (idx >> 2) & 31;
    int tap  = (idx >> 7) % 9;
    int mg   = (idx / 1152) & 15;
    int chunk= (idx / 18432) % 40;
    int l    = idx / 737280;
    int oc   = mg * 16 + (lane >> 2) + 8 * (r & 1);
    int ic   = chunk * 8 + (lane & 3) + 4 * (r >> 1);
    float v = w[(((size_t)(l * 256 + oc)) * 320 + ic) * 9 + tap];
    g_wF[idx] = tf32f(v);
}

// ---------------- merged prep: lat/proj/out A packs, off+attw+val B pack, pos ----------------
__global__ void k_prep(const float* __restrict__ lat_w, const float* __restrict__ proj_w,
                       const float* __restrict__ off_w, const float* __restrict__ attw_w,
                       const float* __restrict__ val_w, const float* __restrict__ out_w,
                       const float* __restrict__ lemb) {
    int idx = blockIdx.x * 256 + threadIdx.x;
    if (idx < 262144) {                 // lateral A-frag pack
        int r = idx & 3, lane = (idx >> 2) & 31, mt = (idx >> 7) & 15;
        int kt8 = (idx >> 11) & 31, l = idx >> 16;
        int row = mt * 16 + (lane >> 2) + 8 * (r & 1);
        int k   = kt8 * 8 + (lane & 3) + 4 * (r >> 1);
        g_latF[idx] = tf32f(lat_w[(size_t)l * 65536 + row * 256 + k]);
    } else if (idx < 327680) {          // proj A-frag pack
        int id = idx - 262144;
        int r = id & 3, lane = (id >> 2) & 31, mt = (id >> 7) & 3;
        int kt8 = (id >> 9) & 31, l = id >> 14;
        int row = mt * 16 + (lane >> 2) + 8 * (r & 1);
        int k   = kt8 * 8 + (lane & 3) + 4 * (r >> 1);
        g_projF[id] = tf32f(proj_w[(size_t)l * 16384 + row * 256 + k]);
    } else if (idx < 417792) {          // off+attw+val B-frag pack (nt 0..175)
        int id = idx - 327680;
        int i = id & 1, lane = (id >> 1) & 31, nt = (id >> 6) % 176, kt8 = id / 11264;
        int n = nt * 8 + (lane >> 2);
        int k = kt8 * 8 + (lane & 3) + 4 * i;
        float v;
        if (n < 1024)       v = off_w[n * 64 + k];
        else if (n < 1280)  v = attw_w[(n - 1024) * 64 + k];
        else if (n < 1344)  v = val_w[(n - 1280) * 64 + k];
        else                v = 0.f;
        g_oaF[id] = tf32f(v);
    } else if (idx < 679936) {          // sine pos + level embed
        int id = idx - 417792;
        int e = id >> 12, q = id & 4095;
        int l = q >> 10, hw = q & 1023, y = hw >> 5, x = hw & 31;
        int e2 = (e < 32) ? e : (e - 32);
        int n  = (e < 32) ? (y + 1) : (x + 1);
        int j  = e2 >> 1;
        float t = powf(10000.f, (float)j * (1.f / 16.f));
        float p = (float)n / t;
        float v = (e2 & 1) ? cosf(p) : sinf(p);
        g_pos[id] = v + lemb[l * 64 + e];
    } else if (idx < 684032) {          // out-proj A-frag pack (4096 entries)
        int id = idx - 679936;
        int r = id & 3, lane = (id >> 2) & 31, mt = (id >> 7) & 3, kt8 = id >> 9;
        int row = mt * 16 + (lane >> 2) + 8 * (r & 1);
        int k   = kt8 * 8 + (lane & 3) + 4 * (r >> 1);
        g_outF[id] = tf32f(out_w[row * 64 + k]);
    }
}

// ---------------- lateral 1x1 conv via TF32 MMA, register-prefetch pipelined ----------------
__global__ __launch_bounds__(256) void k_lat_tc(
    const float* __restrict__ x0, const float* __restrict__ x1,
    const float* __restrict__ x2, const float* __restrict__ x3,
    const float* __restrict__ bias)
{
    __shared__ __align__(16) float AsF[2048];
    __shared__ __align__(16) float Bs[32 * 68];
    int lb = blockIdx.z, l = lb >> 4, b = lb & 15;
    const float* X = (l == 0 ? x0 : l == 1 ? x1 : l == 2 ? x2 : x3) + (size_t)b * 262144;
    const float* AF = g_latF + (size_t)l * 65536;
    int m0 = blockIdx.y * 64, n0 = blockIdx.x * 64;
    int tid = threadIdx.x, lane = tid & 31, w = tid >> 5;
    int warp_m = w >> 2, warp_n = w & 3;
    int n_w = warp_n * 16;
    float acc[2][2][4] = {};
    float4 aReg[2], bReg[2];

#define LAT_LOAD(cc) do {                                                           \
        int k0_ = (cc) * 32;                                                        \
        _Pragma("unroll")                                                           \
        for (int i = 0; i < 2; i++) {                                               \
            int id = tid + i * 256;                                                 \
            aReg[i] = ((const float4*)AF)[((k0_ >> 3) + (id >> 7)) * 512            \
                                          + (m0 >> 4) * 32 + (id & 127)];           \
            int k = id >> 4, n4 = (id & 15) << 2;                                   \
            bReg[i] = *(const float4*)&X[(size_t)(k0_ + k) * 1024 + n0 + n4];       \
        } } while (0)

    LAT_LOAD(0);
    for (int c = 0; c < 8; c++) {
        __syncthreads();
#pragma unroll
        for (int i = 0; i < 2; i++) {
            int id = tid + i * 256;
            ((float4*)AsF)[id] = aReg[i];
            float4 v = bReg[i];
            v.x = tf32f(v.x); v.y = tf32f(v.y); v.z = tf32f(v.z); v.w = tf32f(v.w);
            int k = id >> 4, n4 = (id & 15) << 2;
            *(float4*)&Bs[k * 68 + n4] = v;
        }
        if (c + 1 < 8) LAT_LOAD(c + 1);
        __syncthreads();
#pragma unroll
        for (int kk = 0; kk < 4; kk++) {
            uint4 A0 = *(const uint4*)&AsF[(kk * 4 + warp_m * 2 + 0) * 128 + lane * 4];
            uint4 A1 = *(const uint4*)&AsF[(kk * 4 + warp_m * 2 + 1) * 128 + lane * 4];
#pragma unroll
            for (int j = 0; j < 2; j++) {
                const float* bp = &Bs[(kk * 8 + (lane & 3)) * 68 + n_w + j * 8 + (lane >> 2)];
                unsigned b0 = __float_as_uint(bp[0]);
                unsigned b1 = __float_as_uint(bp[4 * 68]);
                mma_tf32(acc[0][j], A0, b0, b1);
                mma_tf32(acc[1][j], A1, b0, b1);
            }
        }
    }
#undef LAT_LOAD
    float* O = g_lat + (size_t)lb * 262144;
    int row_l = lane >> 2, colp = (lane & 3) << 1;
#pragma unroll
    for (int h = 0; h < 2; h++)
#pragma unroll
        for (int j = 0; j < 2; j++) {
            int row = m0 + warp_m * 32 + h * 16 + row_l;
            int col = n0 + n_w + j * 8 + colp;
            float b0v = bias[l * 256 + row], b1v = bias[l * 256 + row + 8];
            *(float2*)&O[(size_t)row * 1024 + col] =
                make_float2(acc[h][j][0] + b0v, acc[h][j][1] + b0v);
            *(float2*)&O[(size_t)(row + 8) * 1024 + col] =
                make_float2(acc[h][j][2] + b1v, acc[h][j][3] + b1v);
        }
}

// ---------------- proj (256->64) via TF32 MMA + BN + ReLU, register-prefetch ----------------
__global__ __launch_bounds__(256) void k_proj_tc(
    const float* __restrict__ bias,
    const float* __restrict__ bng, const float* __restrict__ bnb,
    const float* __restrict__ bnm, const float* __restrict__ bnv)
{
    __shared__ __align__(16) float AsF[2048];
    __shared__ __align__(16) float Bs[32 * 68];
    int lb = blockIdx.z, l = lb >> 4, b = lb & 15;
    const float* X = g_lat + (size_t)lb * 262144;
    const float* AF = g_projF + (size_t)l * 16384;
    int n0 = blockIdx.x * 64;
    int tid = threadIdx.x, lane = tid & 31, w = tid >> 5;
    int warp_m = w >> 2, warp_n = w & 3;
    int n_w = warp_n * 16;
    float acc[2][2][4] = {};
    float4 aReg[2], bReg[2];

#define PROJ_LOAD(cc) do {                                                          \
        int k0_ = (cc) * 32;                                                        \
        _Pragma("unroll")                                                           \
        for (int i = 0; i < 2; i++) {                                               \
            int id = tid + i * 256;                                                 \
            aReg[i] = ((const float4*)AF)[(((cc) * 4 + (id >> 7)) * 128) + (id & 127)]; \
            int k = id >> 4, n4 = (id & 15) << 2;                                   \
            bReg[i] = *(const float4*)&X[(size_t)(k0_ + k) * 1024 + n0 + n4];       \
        } } while (0)

    PROJ_LOAD(0);
    for (int c = 0; c < 8; c++) {
        __syncthreads();
#pragma unroll
        for (int i = 0; i < 2; i++) {
            int id = tid + i * 256;
            ((float4*)AsF)[id] = aReg[i];
            float4 v = bReg[i];
            v.x = tf32f(v.x); v.y = tf32f(v.y); v.z = tf32f(v.z); v.w = tf32f(v.w);
            int k = id >> 4, n4 = (id & 15) << 2;
            *(float4*)&Bs[k * 68 + n4] = v;
        }
        if (c + 1 < 8) PROJ_LOAD(c + 1);
        __syncthreads();
#pragma unroll
        for (int kk = 0; kk < 4; kk++) {
            uint4 A0 = *(const uint4*)&AsF[(kk * 4 + warp_m * 2 + 0) * 128 + lane * 4];
            uint4 A1 = *(const uint4*)&AsF[(kk * 4 + warp_m * 2 + 1) * 128 + lane * 4];
#pragma unroll
            for (int j = 0; j < 2; j++) {
                const float* bp = &Bs[(kk * 8 + (lane & 3)) * 68 + n_w + j * 8 + (lane >> 2)];
                unsigned b0 = __float_as_uint(bp[0]);
                unsigned b1 = __float_as_uint(bp[4 * 68]);
                mma_tf32(acc[0][j], A0, b0, b1);
                mma_tf32(acc[1][j], A1, b0, b1);
            }
        }
    }
#undef PROJ_LOAD
    int row_l = lane >> 2, colp = (lane & 3) << 1;
#pragma unroll
    for (int h = 0; h < 2; h++) {
        int m = warp_m * 32 + h * 16 + row_l;
        float sc0 = bng[l * 64 + m] * rsqrtf(bnv[l * 64 + m] + 1e-5f);
        float sh0 = bnb[l * 64 + m] - bnm[l * 64 + m] * sc0 + bias[l * 64 + m] * sc0;
        float sc1 = bng[l * 64 + m + 8] * rsqrtf(bnv[l * 64 + m + 8] + 1e-5f);
        float sh1 = bnb[l * 64 + m + 8] - bnm[l * 64 + m + 8] * sc1 + bias[l * 64 + m + 8] * sc1;
#pragma unroll
        for (int j = 0; j < 2; j++) {
            int col = n0 + n_w + j * 8 + colp;
            float* p0 = &g_src[((size_t)b * 64 + m) * 4096 + l * 1024 + col];
            float* p1 = &g_src[((size_t)b * 64 + m + 8) * 4096 + l * 1024 + col];
            *(float2*)p0 = make_float2(fmaxf(acc[h][j][0] * sc0 + sh0, 0.f),
                                       fmaxf(acc[h][j][1] * sc0 + sh0, 0.f));
            *(float2*)p1 = make_float2(fmaxf(acc[h][j][2] * sc1 + sh1, 0.f),
                                       fmaxf(acc[h][j][3] * sc1 + sh1, 0.f));
        }
    }
}

// ---------------- off(1024)+attw(256) GEMM via TF32 MMA: M=q4096, N=1280, K=64 ----------------
__global__ __launch_bounds__(256) void k_off_tc(const float* __restrict__ off_b,
                                                const float* __restrict__ attw_b)
{
    __shared__ __align__(16) float As[64 * 68];
    __shared__ __align__(16) float BsF[4096];
    int b = blockIdx.z;
    int q0 = blockIdx.y * 64, n0 = blockIdx.x * 64;
    int tid = threadIdx.x, lane = tid & 31, w = tid >> 5;
    int warp_m = w >> 2, warp_n = w & 3;
    const float* S = g_src + (size_t)b * 262144;
#pragma unroll
    for (int i = 0; i < 4; i++) {
        int id = tid + i * 256;
        int k = id >> 4, q4 = (id & 15) << 2;
        float4 v = *(const float4*)&S[(size_t)k * 4096 + q0 + q4];
        float4 p = *(const float4*)&g_pos[(size_t)k * 4096 + q0 + q4];
        v.x = tf32f(v.x + p.x); v.y = tf32f(v.y + p.y);
        v.z = tf32f(v.z + p.z); v.w = tf32f(v.w + p.w);
        *(float4*)&As[k * 68 + q4] = v;
    }
#pragma unroll
    for (int i = 0; i < 4; i++) {
        int id = tid + i * 256;
        int kt8 = id >> 7, rem = id & 127;
        ((float4*)BsF)[id] = ((const float4*)g_oaF)[(kt8 * 176 + (n0 >> 3)) * 16 + rem];
    }
    __syncthreads();
    float acc[2][2][4] = {};
#pragma unroll
    for (int kk8 = 0; kk8 < 8; kk8++) {
        uint4 A[2];
#pragma unroll
        for (int h = 0; h < 2; h++) {
            const float* ap = &As[(kk8 * 8 + (lane & 3)) * 68 + warp_m * 32 + h * 16 + (lane >> 2)];
            A[h].x = __float_as_uint(ap[0]);
            A[h].y = __float_as_uint(ap[8]);
            A[h].z = __float_as_uint(ap[4 * 68]);
            A[h].w = __float_as_uint(ap[4 * 68 + 8]);
        }
#pragma unroll
        for (int j = 0; j < 2; j++) {
            float2 bv = *(const float2*)&BsF[(kk8 * 8 + warp_n * 2 + j) * 64 + lane * 2];
            unsigned b0 = __float_as_uint(bv.x), b1 = __float_as_uint(bv.y);
            mma_tf32(acc[0][j], A[0], b0, b1);
            mma_tf32(acc[1][j], A[1], b0, b1);
        }
    }
    int row_l = lane >> 2, colp = (lane & 3) << 1;
    bool is_off = (n0 < 1024);
#pragma unroll
    for (int h = 0; h < 2; h++)
#pragma unroll
        for (int j = 0; j < 2; j++) {
            int q = q0 + warp_m * 32 + h * 16 + row_l;
            int col = n0 + warp_n * 16 + j * 8 + colp;
            if (is_off) {
                float bb0 = off_b[col], bb1 = off_b[col + 1];
                float* op = g_off + ((size_t)b * 4096 + q) * 1024 + col;
                *(float2*)op = make_float2(acc[h][j][0] + bb0, acc[h][j][1] + bb1);
                *(float2*)(op + 8 * 1024) = make_float2(acc[h][j][2] + bb0, acc[h][j][3] + bb1);
            } else {
                int ca = col - 1024;
                float bb0 = attw_b[ca], bb1 = attw_b[ca + 1];
                float* op = g_attw + ((size_t)b * 4096 + q) * 256 + ca;
                *(float2*)op = make_float2(acc[h][j][0] + bb0, acc[h][j][1] + bb1);
                *(float2*)(op + 8 * 256) = make_float2(acc[h][j][2] + bb0, acc[h][j][3] + bb1);
            }
        }
}

// ---------------- value GEMM via TF32 MMA: M=q4096, N=64, K=64 -> g_value [b][q][64] ----------------
__global__ __launch_bounds__(256) void k_val_tc(const float* __restrict__ bias)
{
    __shared__ __align__(16) float As[64 * 68];
    __shared__ __align__(16) float BsF[4096];
    int b = blockIdx.z;
    int q0 = blockIdx.y * 64;
    int tid = threadIdx.x, lane = tid & 31, w = tid >> 5;
    int warp_m = w >> 2, warp_n = w & 3;
    const float* S = g_src + (size_t)b * 262144;
#pragma unroll
    for (int i = 0; i < 4; i++) {
        int id = tid + i * 256;
        int k = id >> 4, q4 = (id & 15) << 2;
        float4 v = *(const float4*)&S[(size_t)k * 4096 + q0 + q4];
        v.x = tf32f(v.x); v.y = tf32f(v.y); v.z = tf32f(v.z); v.w = tf32f(v.w);
        *(float4*)&As[k * 68 + q4] = v;
    }
#pragma unroll
    for (int i = 0; i < 4; i++) {
        int id = tid + i * 256;
        int kt8 = id >> 7, rem = id & 127;
        ((float4*)BsF)[id] = ((const float4*)g_oaF)[(kt8 * 176 + 160 + (rem >> 4)) * 16 + (rem & 15)];
    }
    __syncthreads();
    float acc[2][2][4] = {};
#pragma unroll
    for (int kk8 = 0; kk8 < 8; kk8++) {
        uint4 A[2];
#pragma unroll
        for (int h = 0; h < 2; h++) {
            const float* ap = &As[(kk8 * 8 + (lane & 3)) * 68 + warp_m * 32 + h * 16 + (lane >> 2)];
            A[h].x = __float_as_uint(ap[0]);
            A[h].y = __float_as_uint(ap[8]);
            A[h].z = __float_as_uint(ap[4 * 68]);
            A[h].w = __float_as_uint(ap[4 * 68 + 8]);
        }
#pragma unroll
        for (int j = 0; j < 2; j++) {
            float2 bv = *(const float2*)&BsF[(kk8 * 8 + warp_n * 2 + j) * 64 + lane * 2];
            unsigned b0 = __float_as_uint(bv.x), b1 = __float_as_uint(bv.y);
            mma_tf32(acc[0][j], A[0], b0, b1);
            mma_tf32(acc[1][j], A[1], b0, b1);
        }
    }
    int row_l = lane >> 2, colp = (lane & 3) << 1;
#pragma unroll
    for (int h = 0; h < 2; h++)
#pragma unroll
        for (int j = 0; j < 2; j++) {
            int q = q0 + warp_m * 32 + h * 16 + row_l;
            int col = warp_n * 16 + j * 8 + colp;
            float bb0 = bias[col], bb1 = bias[col + 1];
            float* op = g_value + ((size_t)b * 4096 + q) * 64 + col;
            *(float2*)op = make_float2(acc[h][j][0] + bb0, acc[h][j][1] + bb1);
            *(float2*)(op + 8 * 64) = make_float2(acc[h][j][2] + bb0, acc[h][j][3] + bb1);
        }
}

// ---------------- out-proj via TF32 MMA (lat-style): M=64, K=64, N=4096 per b ----------------
__global__ __launch_bounds__(256) void k_out_tc(const float* __restrict__ bias)
{
    __shared__ __align__(16) float AsF[2048];
    __shared__ __align__(16) float Bs[32 * 68];
    int b = blockIdx.z;
    const float* X = g_attn + (size_t)b * 262144;
    int n0 = blockIdx.x * 64;
    int tid = threadIdx.x, lane = tid & 31, w = tid >> 5;
    int warp_m = w >> 2, warp_n = w & 3;
    int n_w = warp_n * 16;
    float acc[2][2][4] = {};
    for (int c = 0; c < 2; c++) {
        int k0 = c * 32;
        __syncthreads();
#pragma unroll
        for (int i = 0; i < 2; i++) {
            int id = tid + i * 256;
            int kt = id >> 7, rem = id & 127;
            ((float4*)AsF)[id] = ((const float4*)g_outF)[((k0 >> 3) + kt) * 128 + rem];
        }
#pragma unroll
        for (int i = 0; i < 2; i++) {
            int id = tid + i * 256;
            int k = id >> 4, n4 = (id & 15) << 2;
            float4 v = *(const float4*)&X[(size_t)(k0 + k) * 4096 + n0 + n4];
            v.x = tf32f(v.x); v.y = tf32f(v.y); v.z = tf32f(v.z); v.w = tf32f(v.w);
            *(float4*)&Bs[k * 68 + n4] = v;
        }
        __syncthreads();
#pragma unroll
        for (int kk = 0; kk < 4; kk++) {
            uint4 A0 = *(const uint4*)&AsF[(kk * 4 + warp_m * 2 + 0) * 128 + lane * 4];
            uint4 A1 = *(const uint4*)&AsF[(kk * 4 + warp_m * 2 + 1) * 128 + lane * 4];
#pragma unroll
            for (int j = 0; j < 2; j++) {
                const float* bp = &Bs[(kk * 8 + (lane & 3)) * 68 + n_w + j * 8 + (lane >> 2)];
                unsigned b0 = __float_as_uint(bp[0]);
                unsigned b1 = __float_as_uint(bp[4 * 68]);
                mma_tf32(acc[0][j], A0, b0, b1);
                mma_tf32(acc[1][j], A1, b0, b1);
            }
        }
    }
    float* O = g_src2 + (size_t)b * 262144;
    int row_l = lane >> 2, colp = (lane & 3) << 1;
#pragma unroll
    for (int h = 0; h < 2; h++)
#pragma unroll
        for (int j = 0; j < 2; j++) {
            int row = warp_m * 32 + h * 16 + row_l;
            int col = n0 + n_w + j * 8 + colp;
            float b0v = bias[row], b1v = bias[row + 8];
            *(float2*)&O[(size_t)row * 4096 + col] =
                make_float2(acc[h][j][0] + b0v, acc[h][j][1] + b0v);
            *(float2*)&O[(size_t)(row + 8) * 4096 + col] =
                make_float2(acc[h][j][2] + b1v, acc[h][j][3] + b1v);
        }
}

// ---------------- deformable attention sampling ----------------
__global__ void k_sample() {
    int idx = blockIdx.x * 256 + threadIdx.x;
    if (idx >= 16 * 4096 * 8) return;
    int h = idx & 7, q = (idx >> 3) & 4095, b = idx >> 15;
    const float* aw  = g_attw + (size_t)(b * 4096 + q) * 256 + h * 32;
    const float* off = g_off  + (size_t)(b * 4096 + q) * 1024 + h * 64;
    float lg[32];
#pragma unroll
    for (int j = 0; j < 32; j++) lg[j] = aw[j];
    float mx = lg[0];
#pragma unroll
    for (int j = 1; j < 32; j++) mx = fmaxf(mx, lg[j]);
    float s = 0.f;
#pragma unroll
    for (int j = 0; j < 32; j++) { lg[j] = __expf(lg[j] - mx); s += lg[j]; }
    float inv = 1.f / s;
    int y = (q & 1023) >> 5, x = q & 31;
    float rx = (x + 0.5f) * (1.f / 32.f), ry = (y + 0.5f) * (1.f / 32.f);
    float acc[8] = {0, 0, 0, 0, 0, 0, 0, 0};
    const float* vb = g_value + (size_t)b * 4096 * 64 + h * 8;

#define SAMP(XX, YY, WW2) do { int xx = (XX), yy = (YY);                            \
        if (xx >= 0 && xx < 32 && yy >= 0 && yy < 32) {                             \
            const float4* rp = (const float4*)(vl + (size_t)(yy * 32 + xx) * 64);   \
            float4 a = rp[0], c = rp[1]; float wv = (WW2);                          \
            acc[0] += wv * a.x; acc[1] += wv * a.y; acc[2] += wv * a.z; acc[3] += wv * a.w; \
            acc[4] += wv * c.x; acc[5] += wv * c.y; acc[6] += wv * c.z; acc[7] += wv * c.w; } } while (0)

#pragma unroll
    for (int l = 0; l < 4; l++) {
        const float* vl = vb + (size_t)l * 1024 * 64;
#pragma unroll
        for (int p = 0; p < 8; p++) {
            float wgt = lg[l * 8 + p] * inv;
            float fx = (rx + off[l * 16 + p * 2 + 0] * (1.f / 32.f)) * 32.f - 0.5f;
            float fy = (ry + off[l * 16 + p * 2 + 1] * (1.f / 32.f)) * 32.f - 0.5f;
            float x0f = floorf(fx), y0f = floorf(fy);
            int xi = (int)x0f, yi = (int)y0f;
            float wx = fx - x0f, wy = fy - y0f;
            SAMP(xi,     yi,     wgt * (1.f - wx) * (1.f - wy));
            SAMP(xi + 1, yi,     wgt * wx * (1.f - wy));
            SAMP(xi,     yi + 1, wgt * (1.f - wx) * wy);
            SAMP(xi + 1, yi + 1, wgt * wx * wy);
        }
    }
#undef SAMP
#pragma unroll
    for (int d = 0; d < 8; d++)
        g_attn[((size_t)b * 64 + h * 8 + d) * 4096 + q] = acc[d];
}

// ---------------- fuse + bilinear resize -> padded g_nfr (tf32, zero halo) ----------------
__global__ void k_fuse_resize(int l, int oh, int ow, int PH, int PW4,
                              float hs, size_t nfr_off, int count) {
    int idx = blockIdx.x * 256 + threadIdx.x;
    if (idx >= count) return;
    int px = idx % PW4;
    int t = idx / PW4;
    int py = t % PH; t /= PH;
    int c = t % 320;
    int b = t / 320;
    int gy = py - 1, gx = px - 1;
    float res = 0.f;
    if (gy >= 0 && gy < oh && gx >= 0 && gx < ow) {
        float sy = fmaxf((gy + 0.5f) * hs - 0.5f, 0.f);
        float sx = fmaxf((gx + 0.5f) * hs - 0.5f, 0.f);
        int y0 = (int)sy, x0 = (int)sx;
        float fy = sy - y0, fx = sx - x0;
        int y1 = min(y0 + 1, 31), x1 = min(x0 + 1, 31);
        const float* p;
        if (c < 256)
            p = g_lat + ((size_t)(l * 16 + b) * 256 + c) * 1024;
        else
            p = g_src2 + ((size_t)b * 64 + (c - 256)) * 4096 + l * 1024;
        float v00 = p[y0 * 32 + x0], v01 = p[y0 * 32 + x1];
        float v10 = p[y1 * 32 + x0], v11 = p[y1 * 32 + x1];
        float r0 = v00 * (1.f - fy) + v10 * fy;
        float r1 = v01 * (1.f - fy) + v11 * fy;
        res = tf32f(r0 * (1.f - fx) + r1 * fx);
    }
    g_nfr[nfr_off + (size_t)idx] = res;
}

// ---------------- 3x3 conv 320->256 pad1, TF32 MMA, 64oc, shared-B, 2-stage (R12 proven) ----------------
// Block: 64 oc x 16x16 px; 8 warps; warp = ALL 64 oc x (rows 2w,2w+1) x 16 px.
// Dynamic smem: Ws 2x4608 + Is 2x2880 = 59904 B.
__global__ __launch_bounds__(256) void k_conv_tc(int l, int oh, int ow, int PW4, int planesz,
                                                 size_t nfr_off,
                                                 const float* __restrict__ cb,
                                                 float* __restrict__ out, size_t out_off)
{
    extern __shared__ __align__(16) float smem[];
    float* Ws = smem;                 // 2 x 4608 floats
    float* Is = smem + 9216;          // 2 x 2880 floats
    int b = blockIdx.z;
    int ocb = blockIdx.y;             // 0..3 -> 64 oc
    int tiles_x = ow >> 4;
    int py0 = (blockIdx.x / tiles_x) << 4;
    int px0 = (blockIdx.x % tiles_x) << 4;
    int tid = threadIdx.x;
    int lane = tid & 31, w = tid >> 5;
    int r0 = w * 2;
    int ohow = oh * ow;
    const float4* wsrc = (const float4*)g_wF
                       + (size_t)l * 184320 + (size_t)ocb * 1152;
    const float* ibase = g_nfr + nfr_off + (size_t)b * 320 * planesz;
    float acc[4][4][4] = {};

    // per-thread input staging ops (loop-invariant, <=3 entries — registers)
    int nops = 0;
    int s_off[3];
    int g_ofs[3];
#pragma unroll
    for (int i = tid; i < 720; i += 256) {
        int kc = i / 90, r2 = i - kc * 90;
        int iy = r2 / 5, s = r2 - iy * 5;
        s_off[nops] = kc * 360 + iy * 20 + s * 4;
        g_ofs[nops] = kc * planesz + (py0 + iy) * PW4 + px0 + s * 4;
        nops++;
    }

#define ISSUE_STAGE(stage, buf) do {                                           \
        const float* chb = ibase + (size_t)((stage) * 8) * planesz;            \
        float* isb_ = Is + (buf) * 2880;                                       \
        for (int j2 = 0; j2 < nops; j2++) cp16(isb_ + s_off[j2], chb + g_ofs[j2]); \
        const float4* wc = wsrc + (size_t)(stage) * 4608;                      \
        float4* wd = (float4*)(Ws + (buf) * 4608);                             \
        _Pragma("unroll")                                                      \
        for (int i2 = 0; i2 < 5; i2++) {                                       \
            int k = tid + i2 * 256;                                            \
            if (k < 1152) cp16(&wd[k], &wc[k]);                                \
        }                                                                      \
        cp_commit(); } while (0)

    ISSUE_STAGE(0, 0);
    ISSUE_STAGE(1, 1);

    for (int c = 0; c < 40; c++) {
        int buf = c & 1;
        if (c < 39) { asm volatile("cp.async.wait_group 1;\n"); }
        else        { asm volatile("cp.async.wait_group 0;\n"); }
        __syncthreads();
        const float* wsA = Ws + buf * 4608 + lane * 4;
        const float* isb = Is + buf * 2880 + (lane & 3) * 360 + (lane >> 2);
#pragma unroll
        for (int tap = 0; tap < 9; tap++) {
            int dy = tap / 3, dx = tap - dy * 3;
            uint4 A0 = *(const uint4*)(wsA + tap * 128);
            uint4 A1 = *(const uint4*)(wsA + 1152 + tap * 128);
            uint4 A2 = *(const uint4*)(wsA + 2304 + tap * 128);
            uint4 A3 = *(const uint4*)(wsA + 3456 + tap * 128);
            const float* ib = isb + (r0 + dy) * 20 + dx;
#pragma unroll
            for (int j = 0; j < 4; j++) {
                const float* bp = ib + (j >> 1) * 20 + ((j & 1) << 3);
                unsigned b0 = __float_as_uint(bp[0]);
                unsigned b1 = __float_as_uint(bp[4 * 360]);
                mma_tf32(acc[0][j], A0, b0, b1);
                mma_tf32(acc[1][j], A1, b0, b1);
                mma_tf32(acc[2][j], A2, b0, b1);
                mma_tf32(acc[3][j], A3, b0, b1);
            }
        }
        __syncthreads();
        if (c + 2 < 40) ISSUE_STAGE(c + 2, buf);
    }
#undef ISSUE_STAGE

    // epilogue
    int row = lane >> 2, colp = (lane & 3) << 1;
    int oc0 = ocb * 64;
#pragma unroll
    for (int m = 0; m < 4; m++) {
        int ocA = oc0 + m * 16 + row;
        float bA = cb[l * 256 + ocA];
        float bB = cb[l * 256 + ocA + 8];
        float* outA = out + out_off + (size_t)(b * 256 + ocA) * ohow;
        float* outB = outA + (size_t)8 * ohow;
#pragma unroll
        for (int j = 0; j < 4; j++) {
            int gy = py0 + r0 + (j >> 1);
            int gx = px0 + ((j & 1) << 3) + colp;
            float2 v0 = make_float2(acc[m][j][0] + bA, acc[m][j][1] + bA);
            float2 v1 = make_float2(acc[m][j][2] + bB, acc[m][j][3] + bB);
            *(float2*)(outA + gy * ow + gx) = v0;
            *(float2*)(outB + gy * ow + gx) = v1;
        }
    }
}

// ---------------- launch ----------------
extern "C" void kernel_launch(void* const* d_in, const int* in_sizes, int n_in,
                              void* d_out, int out_size)
{
    const float* x0     = (const float*)d_in[0];
    const float* x1     = (const float*)d_in[1];
    const float* x2     = (const float*)d_in[2];
    const float* x3     = (const float*)d_in[3];
    const float* lat_w  = (const float*)d_in[4];
    const float* lat_b  = (const float*)d_in[5];
    const float* proj_w = (const float*)d_in[6];
    const float* proj_b = (const float*)d_in[7];
    const float* bn_g   = (const float*)d_in[8];
    const float* bn_b   = (const float*)d_in[9];
    const float* bn_m   = (const float*)d_in[10];
    const float* bn_v   = (const float*)d_in[11];
    const float* conv_w = (const float*)d_in[12];
    const float* conv_b = (const float*)d_in[13];
    const float* lemb   = (const float*)d_in[14];
    const float* off_w  = (const float*)d_in[15];
    const float* off_b  = (const float*)d_in[16];
    const float* attw_w = (const float*)d_in[17];
    const float* attw_b = (const float*)d_in[18];
    const float* val_w  = (const float*)d_in[19];
    const float* val_b  = (const float*)d_in[20];
    const float* out_w  = (const float*)d_in[21];
    const float* out_b  = (const float*)d_in[22];
    float* out = (float*)d_out;

    // idempotent, unconditional (no static guards): allow 59904 B dynamic smem
    cudaFuncSetAttribute(k_conv_tc, cudaFuncAttributeMaxDynamicSharedMemorySize, 61440);

    k_wtrans<<<11520, 256>>>(conv_w);
    k_prep<<<2672, 256>>>(lat_w, proj_w, off_w, attw_w, val_w, out_w, lemb);
    k_lat_tc<<<dim3(16, 4, 64), 256>>>(x0, x1, x2, x3, lat_b);
    k_proj_tc<<<dim3(16, 1, 64), 256>>>(proj_b, bn_g, bn_b, bn_m, bn_v);
    k_val_tc<<<dim3(1, 64, 16), 256>>>(val_b);
    k_off_tc<<<dim3(20, 64, 16), 256>>>(off_b, attw_b);
    k_sample<<<2048, 256>>>();
    k_out_tc<<<dim3(64, 1, 16), 256>>>(out_b);

    const int    OHS[4]  = {16, 32, 64, 128};
    const int    PW4S[4] = {20, 36, 68, 132};
    const int    PLSZ[4] = {360, 1224, 4488, 17160};
    const size_t NFR[4]  = {0, 1843200, 8110080, 31088640};
    const size_t OUT[4]  = {0, 1048576, 5242880, 22020096};
    for (int l = 0; l < 4; l++) {
        int oh = OHS[l], ow = oh;
        int PH = oh + 2, PW4 = PW4S[l];
        int count = 16 * 320 * PH * PW4;
        float hs = 32.0f / (float)oh;
        k_fuse_resize<<<count / 256, 256>>>(l, oh, ow, PH, PW4, hs, NFR[l], count);
    }
    for (int l = 0; l < 4; l++) {
        int oh = OHS[l], ow = oh;
        dim3 grid((oh / 16) * (ow / 16), 4, 16);
        k_conv_tc<<<grid, 256, 59904>>>(l, oh, ow, PW4S[l], PLSZ[l], NFR[l],
                                        conv_b, out, OUT[l]);
    }
}

// round 16
// speedup vs baseline: 1.0226x; 1.0165x over previous
#include <cuda_runtime.h>
#include <cuda_fp16.h>
#include <math.h>

// ---------------- problem constants ----------------
// B=16, L=4 levels (all 32x32), C=256, EMB=64, Lq=4096, HEADS=8, PTS=8, DH=8
// conv: 320ch -> 256ch, 3x3 pad1 on grids 16/32/64/128

// ---------------- device scratch ----------------
__device__ float g_lat  [16777216];   // [l*16+b][256][1024]
__device__ float g_src  [4194304];    // [b][64][4096]
__device__ float g_pos  [262144];     // [64][4096]
__device__ float g_value[4194304];    // [b][4096][64]
__device__ __half g_offH[67108864];   // [b][4096][1024] sampling offsets, fp16
__device__ float g_attw [16777216];   // [b][4096][256]
__device__ float g_attn [4194304];    // [b][64][4096]
__device__ float g_src2 [4194304];    // [b][64][4096]
__device__ float g_wF   [2949120];    // conv weights tf32 frag order [l][chunk40][mg16][tap9][lane32][4]
__device__ float g_latF [262144];     // lat weights tf32 A-frag [l][kt8 32][mt 16][lane32][4]
__device__ float g_projF[65536];      // proj weights tf32 A-frag [l][kt8 32][mt 4][lane32][4]
__device__ float g_outF [4096];       // out weights tf32 A-frag [kt8 8][mt 4][lane32][4]
__device__ float g_oaF  [90112];      // off(128)+attw(32)+val(8)+spare(8) nt=176 tf32 B-frag [kt8 8][nt 176][lane32][2]
__device__ float g_nfr  [118947840];  // padded resized nf (tf32): [b][320][oh+2][ow+4]

__device__ __forceinline__ unsigned f2tf32(float v) {
    unsigned o;
    asm("cvt.rna.tf32.f32 %0, %1;" : "=r"(o) : "f"(v));
    return o;
}
__device__ __forceinline__ float tf32f(float v) { return __uint_as_float(f2tf32(v)); }

__device__ __forceinline__ void mma_tf32(float* c, uint4 a, unsigned b0, unsigned b1) {
    asm volatile("mma.sync.aligned.m16n8k8.row.col.f32.tf32.tf32.f32 "
        "{%0,%1,%2,%3}, {%4,%5,%6,%7}, {%8,%9}, {%0,%1,%2,%3};\n"
        : "+f"(c[0]), "+f"(c[1]), "+f"(c[2]), "+f"(c[3])
        : "r"(a.x), "r"(a.y), "r"(a.z), "r"(a.w), "r"(b0), "r"(b1));
}
__device__ __forceinline__ void cp16(void* dst, const void* src) {
    unsigned d = (unsigned)__cvta_generic_to_shared(dst);
    asm volatile("cp.async.cg.shared.global [%0], [%1], 16;\n" :: "r"(d), "l"(src));
}
__device__ __forceinline__ void cp_commit() { asm volatile("cp.async.commit_group;\n"); }

// ---------------- conv weight repack: fragment-order + tf32 ----------------
__global__ void k_wtrans(const float* __restrict__ w) {
    int idx = blockIdx.x * 256 + threadIdx.x;
    if (idx >= 4 * 40 * 16 * 9 * 32 * 4) return;
    int r    = idx & 3;
    int lane = (idx >> 2) & 31;
    int tap  = (idx >> 7) % 9;
    int mg   = (idx / 1152) & 15;
    int chunk= (idx / 18432) % 40;
    int l    = idx / 737280;
    int oc   = mg * 16 + (lane >> 2) + 8 * (r & 1);
    int ic   = chunk * 8 + (lane & 3) + 4 * (r >> 1);
    float v = w[(((size_t)(l * 256 + oc)) * 320 + ic) * 9 + tap];
    g_wF[idx] = tf32f(v);
}

// ---------------- merged prep: lat/proj/out A packs, off+attw+val B pack, pos ----------------
__global__ void k_prep(const float* __restrict__ lat_w, const float* __restrict__ proj_w,
                       const float* __restrict__ off_w, const float* __restrict__ attw_w,
                       const float* __restrict__ val_w, const float* __restrict__ out_w,
                       const float* __restrict__ lemb) {
    int idx = blockIdx.x * 256 + threadIdx.x;
    if (idx < 262144) {                 // lateral A-frag pack
        int r = idx & 3, lane = (idx >> 2) & 31, mt = (idx >> 7) & 15;
        int kt8 = (idx >> 11) & 31, l = idx >> 16;
        int row = mt * 16 + (lane >> 2) + 8 * (r & 1);
        int k   = kt8 * 8 + (lane & 3) + 4 * (r >> 1);
        g_latF[idx] = tf32f(lat_w[(size_t)l * 65536 + row * 256 + k]);
    } else if (idx < 327680) {          // proj A-frag pack
        int id = idx - 262144;
        int r = id & 3, lane = (id >> 2) & 31, mt = (id >> 7) & 3;
        int kt8 = (id >> 9) & 31, l = id >> 14;
        int row = mt * 16 + (lane >> 2) + 8 * (r & 1);
        int k   = kt8 * 8 + (lane & 3) + 4 * (r >> 1);
        g_projF[id] = tf32f(proj_w[(size_t)l * 16384 + row * 256 + k]);
    } else if (idx < 417792) {          // off+attw+val B-frag pack (nt 0..175)
        int id = idx - 327680;
        int i = id & 1, lane = (id >> 1) & 31, nt = (id >> 6) % 176, kt8 = id / 11264;
        int n = nt * 8 + (lane >> 2);
        int k = kt8 * 8 + (lane & 3) + 4 * i;
        float v;
        if (n < 1024)       v = off_w[n * 64 + k];
        else if (n < 1280)  v = attw_w[(n - 1024) * 64 + k];
        else if (n < 1344)  v = val_w[(n - 1280) * 64 + k];
        else                v = 0.f;
        g_oaF[id] = tf32f(v);
    } else if (idx < 679936) {          // sine pos + level embed
        int id = idx - 417792;
        int e = id >> 12, q = id & 4095;
        int l = q >> 10, hw = q & 1023, y = hw >> 5, x = hw & 31;
        int e2 = (e < 32) ? e : (e - 32);
        int n  = (e < 32) ? (y + 1) : (x + 1);
        int j  = e2 >> 1;
        float t = powf(10000.f, (float)j * (1.f / 16.f));
        float p = (float)n / t;
        float v = (e2 & 1) ? cosf(p) : sinf(p);
        g_pos[id] = v + lemb[l * 64 + e];
    } else if (idx < 684032) {          // out-proj A-frag pack (4096 entries)
        int id = idx - 679936;
        int r = id & 3, lane = (id >> 2) & 31, mt = (id >> 7) & 3, kt8 = id >> 9;
        int row = mt * 16 + (lane >> 2) + 8 * (r & 1);
        int k   = kt8 * 8 + (lane & 3) + 4 * (r >> 1);
        g_outF[id] = tf32f(out_w[row * 64 + k]);
    }
}

// ---------------- lateral 1x1 conv via TF32 MMA, register-prefetch pipelined ----------------
__global__ __launch_bounds__(256) void k_lat_tc(
    const float* __restrict__ x0, const float* __restrict__ x1,
    const float* __restrict__ x2, const float* __restrict__ x3,
    const float* __restrict__ bias)
{
    __shared__ __align__(16) float AsF[2048];
    __shared__ __align__(16) float Bs[32 * 68];
    int lb = blockIdx.z, l = lb >> 4, b = lb & 15;
    const float* X = (l == 0 ? x0 : l == 1 ? x1 : l == 2 ? x2 : x3) + (size_t)b * 262144;
    const float* AF = g_latF + (size_t)l * 65536;
    int m0 = blockIdx.y * 64, n0 = blockIdx.x * 64;
    int tid = threadIdx.x, lane = tid & 31, w = tid >> 5;
    int warp_m = w >> 2, warp_n = w & 3;
    int n_w = warp_n * 16;
    float acc[2][2][4] = {};
    float4 aReg[2], bReg[2];

#define LAT_LOAD(cc) do {                                                           \
        int k0_ = (cc) * 32;                                                        \
        _Pragma("unroll")                                                           \
        for (int i = 0; i < 2; i++) {                                               \
            int id = tid + i * 256;                                                 \
            aReg[i] = ((const float4*)AF)[((k0_ >> 3) + (id >> 7)) * 512            \
                                          + (m0 >> 4) * 32 + (id & 127)];           \
            int k = id >> 4, n4 = (id & 15) << 2;                                   \
            bReg[i] = *(const float4*)&X[(size_t)(k0_ + k) * 1024 + n0 + n4];       \
        } } while (0)

    LAT_LOAD(0);
    for (int c = 0; c < 8; c++) {
        __syncthreads();
#pragma unroll
        for (int i = 0; i < 2; i++) {
            int id = tid + i * 256;
            ((float4*)AsF)[id] = aReg[i];
            float4 v = bReg[i];
            v.x = tf32f(v.x); v.y = tf32f(v.y); v.z = tf32f(v.z); v.w = tf32f(v.w);
            int k = id >> 4, n4 = (id & 15) << 2;
            *(float4*)&Bs[k * 68 + n4] = v;
        }
        if (c + 1 < 8) LAT_LOAD(c + 1);
        __syncthreads();
#pragma unroll
        for (int kk = 0; kk < 4; kk++) {
            uint4 A0 = *(const uint4*)&AsF[(kk * 4 + warp_m * 2 + 0) * 128 + lane * 4];
            uint4 A1 = *(const uint4*)&AsF[(kk * 4 + warp_m * 2 + 1) * 128 + lane * 4];
#pragma unroll
            for (int j = 0; j < 2; j++) {
                const float* bp = &Bs[(kk * 8 + (lane & 3)) * 68 + n_w + j * 8 + (lane >> 2)];
                unsigned b0 = __float_as_uint(bp[0]);
                unsigned b1 = __float_as_uint(bp[4 * 68]);
                mma_tf32(acc[0][j], A0, b0, b1);
                mma_tf32(acc[1][j], A1, b0, b1);
            }
        }
    }
#undef LAT_LOAD
    float* O = g_lat + (size_t)lb * 262144;
    int row_l = lane >> 2, colp = (lane & 3) << 1;
#pragma unroll
    for (int h = 0; h < 2; h++)
#pragma unroll
        for (int j = 0; j < 2; j++) {
            int row = m0 + warp_m * 32 + h * 16 + row_l;
            int col = n0 + n_w + j * 8 + colp;
            float b0v = bias[l * 256 + row], b1v = bias[l * 256 + row + 8];
            *(float2*)&O[(size_t)row * 1024 + col] =
                make_float2(acc[h][j][0] + b0v, acc[h][j][1] + b0v);
            *(float2*)&O[(size_t)(row + 8) * 1024 + col] =
                make_float2(acc[h][j][2] + b1v, acc[h][j][3] + b1v);
        }
}

// ---------------- proj (256->64) via TF32 MMA + BN + ReLU, register-prefetch ----------------
__global__ __launch_bounds__(256) void k_proj_tc(
    const float* __restrict__ bias,
    const float* __restrict__ bng, const float* __restrict__ bnb,
    const float* __restrict__ bnm, const float* __restrict__ bnv)
{
    __shared__ __align__(16) float AsF[2048];
    __shared__ __align__(16) float Bs[32 * 68];
    int lb = blockIdx.z, l = lb >> 4, b = lb & 15;
    const float* X = g_lat + (size_t)lb * 262144;
    const float* AF = g_projF + (size_t)l * 16384;
    int n0 = blockIdx.x * 64;
    int tid = threadIdx.x, lane = tid & 31, w = tid >> 5;
    int warp_m = w >> 2, warp_n = w & 3;
    int n_w = warp_n * 16;
    float acc[2][2][4] = {};
    float4 aReg[2], bReg[2];

#define PROJ_LOAD(cc) do {                                                          \
        int k0_ = (cc) * 32;                                                        \
        _Pragma("unroll")                                                           \
        for (int i = 0; i < 2; i++) {                                               \
            int id = tid + i * 256;                                                 \
            aReg[i] = ((const float4*)AF)[(((cc) * 4 + (id >> 7)) * 128) + (id & 127)]; \
            int k = id >> 4, n4 = (id & 15) << 2;                                   \
            bReg[i] = *(const float4*)&X[(size_t)(k0_ + k) * 1024 + n0 + n4];       \
        } } while (0)

    PROJ_LOAD(0);
    for (int c = 0; c < 8; c++) {
        __syncthreads();
#pragma unroll
        for (int i = 0; i < 2; i++) {
            int id = tid + i * 256;
            ((float4*)AsF)[id] = aReg[i];
            float4 v = bReg[i];
            v.x = tf32f(v.x); v.y = tf32f(v.y); v.z = tf32f(v.z); v.w = tf32f(v.w);
            int k = id >> 4, n4 = (id & 15) << 2;
            *(float4*)&Bs[k * 68 + n4] = v;
        }
        if (c + 1 < 8) PROJ_LOAD(c + 1);
        __syncthreads();
#pragma unroll
        for (int kk = 0; kk < 4; kk++) {
            uint4 A0 = *(const uint4*)&AsF[(kk * 4 + warp_m * 2 + 0) * 128 + lane * 4];
            uint4 A1 = *(const uint4*)&AsF[(kk * 4 + warp_m * 2 + 1) * 128 + lane * 4];
#pragma unroll
            for (int j = 0; j < 2; j++) {
                const float* bp = &Bs[(kk * 8 + (lane & 3)) * 68 + n_w + j * 8 + (lane >> 2)];
                unsigned b0 = __float_as_uint(bp[0]);
                unsigned b1 = __float_as_uint(bp[4 * 68]);
                mma_tf32(acc[0][j], A0, b0, b1);
                mma_tf32(acc[1][j], A1, b0, b1);
            }
        }
    }
#undef PROJ_LOAD
    int row_l = lane >> 2, colp = (lane & 3) << 1;
#pragma unroll
    for (int h = 0; h < 2; h++) {
        int m = warp_m * 32 + h * 16 + row_l;
        float sc0 = bng[l * 64 + m] * rsqrtf(bnv[l * 64 + m] + 1e-5f);
        float sh0 = bnb[l * 64 + m] - bnm[l * 64 + m] * sc0 + bias[l * 64 + m] * sc0;
        float sc1 = bng[l * 64 + m + 8] * rsqrtf(bnv[l * 64 + m + 8] + 1e-5f);
        float sh1 = bnb[l * 64 + m + 8] - bnm[l * 64 + m + 8] * sc1 + bias[l * 64 + m + 8] * sc1;
#pragma unroll
        for (int j = 0; j < 2; j++) {
            int col = n0 + n_w + j * 8 + colp;
            float* p0 = &g_src[((size_t)b * 64 + m) * 4096 + l * 1024 + col];
            float* p1 = &g_src[((size_t)b * 64 + m + 8) * 4096 + l * 1024 + col];
            *(float2*)p0 = make_float2(fmaxf(acc[h][j][0] * sc0 + sh0, 0.f),
                                       fmaxf(acc[h][j][1] * sc0 + sh0, 0.f));
            *(float2*)p1 = make_float2(fmaxf(acc[h][j][2] * sc1 + sh1, 0.f),
                                       fmaxf(acc[h][j][3] * sc1 + sh1, 0.f));
        }
    }
}

// ---------------- off(1024,fp16 out)+attw(256) GEMM via TF32 MMA: M=q4096, N=1280, K=64 ----------------
__global__ __launch_bounds__(256) void k_off_tc(const float* __restrict__ off_b,
                                                const float* __restrict__ attw_b)
{
    __shared__ __align__(16) float As[64 * 68];
    __shared__ __align__(16) float BsF[4096];
    int b = blockIdx.z;
    int q0 = blockIdx.y * 64, n0 = blockIdx.x * 64;
    int tid = threadIdx.x, lane = tid & 31, w = tid >> 5;
    int warp_m = w >> 2, warp_n = w & 3;
    const float* S = g_src + (size_t)b * 262144;
#pragma unroll
    for (int i = 0; i < 4; i++) {
        int id = tid + i * 256;
        int k = id >> 4, q4 = (id & 15) << 2;
        float4 v = *(const float4*)&S[(size_t)k * 4096 + q0 + q4];
        float4 p = *(const float4*)&g_pos[(size_t)k * 4096 + q0 + q4];
        v.x = tf32f(v.x + p.x); v.y = tf32f(v.y + p.y);
        v.z = tf32f(v.z + p.z); v.w = tf32f(v.w + p.w);
        *(float4*)&As[k * 68 + q4] = v;
    }
#pragma unroll
    for (int i = 0; i < 4; i++) {
        int id = tid + i * 256;
        int kt8 = id >> 7, rem = id & 127;
        ((float4*)BsF)[id] = ((const float4*)g_oaF)[(kt8 * 176 + (n0 >> 3)) * 16 + rem];
    }
    __syncthreads();
    float acc[2][2][4] = {};
#pragma unroll
    for (int kk8 = 0; kk8 < 8; kk8++) {
        uint4 A[2];
#pragma unroll
        for (int h = 0; h < 2; h++) {
            const float* ap = &As[(kk8 * 8 + (lane & 3)) * 68 + warp_m * 32 + h * 16 + (lane >> 2)];
            A[h].x = __float_as_uint(ap[0]);
            A[h].y = __float_as_uint(ap[8]);
            A[h].z = __float_as_uint(ap[4 * 68]);
            A[h].w = __float_as_uint(ap[4 * 68 + 8]);
        }
#pragma unroll
        for (int j = 0; j < 2; j++) {
            float2 bv = *(const float2*)&BsF[(kk8 * 8 + warp_n * 2 + j) * 64 + lane * 2];
            unsigned b0 = __float_as_uint(bv.x), b1 = __float_as_uint(bv.y);
            mma_tf32(acc[0][j], A[0], b0, b1);
            mma_tf32(acc[1][j], A[1], b0, b1);
        }
    }
    int row_l = lane >> 2, colp = (lane & 3) << 1;
    bool is_off = (n0 < 1024);
#pragma unroll
    for (int h = 0; h < 2; h++)
#pragma unroll
        for (int j = 0; j < 2; j++) {
            int q = q0 + warp_m * 32 + h * 16 + row_l;
            int col = n0 + warp_n * 16 + j * 8 + colp;
            if (is_off) {
                float bb0 = off_b[col], bb1 = off_b[col + 1];
                __half* op = g_offH + ((size_t)b * 4096 + q) * 1024 + col;
                *(__half2*)op = __floats2half2_rn(acc[h][j][0] + bb0, acc[h][j][1] + bb1);
                *(__half2*)(op + 8 * 1024) = __floats2half2_rn(acc[h][j][2] + bb0, acc[h][j][3] + bb1);
            } else {
                int ca = col - 1024;
                float bb0 = attw_b[ca], bb1 = attw_b[ca + 1];
                float* op = g_attw + ((size_t)b * 4096 + q) * 256 + ca;
                *(float2*)op = make_float2(acc[h][j][0] + bb0, acc[h][j][1] + bb1);
                *(float2*)(op + 8 * 256) = make_float2(acc[h][j][2] + bb0, acc[h][j][3] + bb1);
            }
        }
}

// ---------------- value GEMM via TF32 MMA: M=q4096, N=64, K=64 -> g_value [b][q][64] ----------------
__global__ __launch_bounds__(256) void k_val_tc(const float* __restrict__ bias)
{
    __shared__ __align__(16) float As[64 * 68];
    __shared__ __align__(16) float BsF[4096];
    int b = blockIdx.z;
    int q0 = blockIdx.y * 64;
    int tid = threadIdx.x, lane = tid & 31, w = tid >> 5;
    int warp_m = w >> 2, warp_n = w & 3;
    const float* S = g_src + (size_t)b * 262144;
#pragma unroll
    for (int i = 0; i < 4; i++) {
        int id = tid + i * 256;
        int k = id >> 4, q4 = (id & 15) << 2;
        float4 v = *(const float4*)&S[(size_t)k * 4096 + q0 + q4];
        v.x = tf32f(v.x); v.y = tf32f(v.y); v.z = tf32f(v.z); v.w = tf32f(v.w);
        *(float4*)&As[k * 68 + q4] = v;
    }
#pragma unroll
    for (int i = 0; i < 4; i++) {
        int id = tid + i * 256;
        int kt8 = id >> 7, rem = id & 127;
        ((float4*)BsF)[id] = ((const float4*)g_oaF)[(kt8 * 176 + 160 + (rem >> 4)) * 16 + (rem & 15)];
    }
    __syncthreads();
    float acc[2][2][4] = {};
#pragma unroll
    for (int kk8 = 0; kk8 < 8; kk8++) {
        uint4 A[2];
#pragma unroll
        for (int h = 0; h < 2; h++) {
            const float* ap = &As[(kk8 * 8 + (lane & 3)) * 68 + warp_m * 32 + h * 16 + (lane >> 2)];
            A[h].x = __float_as_uint(ap[0]);
            A[h].y = __float_as_uint(ap[8]);
            A[h].z = __float_as_uint(ap[4 * 68]);
            A[h].w = __float_as_uint(ap[4 * 68 + 8]);
        }
#pragma unroll
        for (int j = 0; j < 2; j++) {
            float2 bv = *(const float2*)&BsF[(kk8 * 8 + warp_n * 2 + j) * 64 + lane * 2];
            unsigned b0 = __float_as_uint(bv.x), b1 = __float_as_uint(bv.y);
            mma_tf32(acc[0][j], A[0], b0, b1);
            mma_tf32(acc[1][j], A[1], b0, b1);
        }
    }
    int row_l = lane >> 2, colp = (lane & 3) << 1;
#pragma unroll
    for (int h = 0; h < 2; h++)
#pragma unroll
        for (int j = 0; j < 2; j++) {
            int q = q0 + warp_m * 32 + h * 16 + row_l;
            int col = warp_n * 16 + j * 8 + colp;
            float bb0 = bias[col], bb1 = bias[col + 1];
            float* op = g_value + ((size_t)b * 4096 + q) * 64 + col;
            *(float2*)op = make_float2(acc[h][j][0] + bb0, acc[h][j][1] + bb1);
            *(float2*)(op + 8 * 64) = make_float2(acc[h][j][2] + bb0, acc[h][j][3] + bb1);
        }
}

// ---------------- out-proj via TF32 MMA (lat-style): M=64, K=64, N=4096 per b ----------------
__global__ __launch_bounds__(256) void k_out_tc(const float* __restrict__ bias)
{
    __shared__ __align__(16) float AsF[2048];
    __shared__ __align__(16) float Bs[32 * 68];
    int b = blockIdx.z;
    const float* X = g_attn + (size_t)b * 262144;
    int n0 = blockIdx.x * 64;
    int tid = threadIdx.x, lane = tid & 31, w = tid >> 5;
    int warp_m = w >> 2, warp_n = w & 3;
    int n_w = warp_n * 16;
    float acc[2][2][4] = {};
    for (int c = 0; c < 2; c++) {
        int k0 = c * 32;
        __syncthreads();
#pragma unroll
        for (int i = 0; i < 2; i++) {
            int id = tid + i * 256;
            int kt = id >> 7, rem = id & 127;
            ((float4*)AsF)[id] = ((const float4*)g_outF)[((k0 >> 3) + kt) * 128 + rem];
        }
#pragma unroll
        for (int i = 0; i < 2; i++) {
            int id = tid + i * 256;
            int k = id >> 4, n4 = (id & 15) << 2;
            float4 v = *(const float4*)&X[(size_t)(k0 + k) * 4096 + n0 + n4];
            v.x = tf32f(v.x); v.y = tf32f(v.y); v.z = tf32f(v.z); v.w = tf32f(v.w);
            *(float4*)&Bs[k * 68 + n4] = v;
        }
        __syncthreads();
#pragma unroll
        for (int kk = 0; kk < 4; kk++) {
            uint4 A0 = *(const uint4*)&AsF[(kk * 4 + warp_m * 2 + 0) * 128 + lane * 4];
            uint4 A1 = *(const uint4*)&AsF[(kk * 4 + warp_m * 2 + 1) * 128 + lane * 4];
#pragma unroll
            for (int j = 0; j < 2; j++) {
                const float* bp = &Bs[(kk * 8 + (lane & 3)) * 68 + n_w + j * 8 + (lane >> 2)];
                unsigned b0 = __float_as_uint(bp[0]);
                unsigned b1 = __float_as_uint(bp[4 * 68]);
                mma_tf32(acc[0][j], A0, b0, b1);
                mma_tf32(acc[1][j], A1, b0, b1);
            }
        }
    }
    float* O = g_src2 + (size_t)b * 262144;
    int row_l = lane >> 2, colp = (lane & 3) << 1;
#pragma unroll
    for (int h = 0; h < 2; h++)
#pragma unroll
        for (int j = 0; j < 2; j++) {
            int row = warp_m * 32 + h * 16 + row_l;
            int col = n0 + n_w + j * 8 + colp;
            float b0v = bias[row], b1v = bias[row + 8];
            *(float2*)&O[(size_t)row * 4096 + col] =
                make_float2(acc[h][j][0] + b0v, acc[h][j][1] + b0v);
            *(float2*)&O[(size_t)(row + 8) * 4096 + col] =
                make_float2(acc[h][j][2] + b1v, acc[h][j][3] + b1v);
        }
}

// ---------------- deformable attention sampling (fp16 offsets) ----------------
__global__ void k_sample() {
    int idx = blockIdx.x * 256 + threadIdx.x;
    if (idx >= 16 * 4096 * 8) return;
    int h = idx & 7, q = (idx >> 3) & 4095, b = idx >> 15;
    const float* aw = g_attw + (size_t)(b * 4096 + q) * 256 + h * 32;
    const __half2* off2 = (const __half2*)(g_offH + (size_t)(b * 4096 + q) * 1024 + h * 64);
    float lg[32];
#pragma unroll
    for (int j = 0; j < 32; j++) lg[j] = aw[j];
    float mx = lg[0];
#pragma unroll
    for (int j = 1; j < 32; j++) mx = fmaxf(mx, lg[j]);
    float s = 0.f;
#pragma unroll
    for (int j = 0; j < 32; j++) { lg[j] = __expf(lg[j] - mx); s += lg[j]; }
    float inv = 1.f / s;
    int y = (q & 1023) >> 5, x = q & 31;
    float rx = (x + 0.5f) * (1.f / 32.f), ry = (y + 0.5f) * (1.f / 32.f);
    float acc[8] = {0, 0, 0, 0, 0, 0, 0, 0};
    const float* vb = g_value + (size_t)b * 4096 * 64 + h * 8;

#define SAMP(XX, YY, WW2) do { int xx = (XX), yy = (YY);                            \
        if (xx >= 0 && xx < 32 && yy >= 0 && yy < 32) {                             \
            const float4* rp = (const float4*)(vl + (size_t)(yy * 32 + xx) * 64);   \
            float4 a = rp[0], c = rp[1]; float wv = (WW2);                          \
            acc[0] += wv * a.x; acc[1] += wv * a.y; acc[2] += wv * a.z; acc[3] += wv * a.w; \
            acc[4] += wv * c.x; acc[5] += wv * c.y; acc[6] += wv * c.z; acc[7] += wv * c.w; } } while (0)

#pragma unroll
    for (int l = 0; l < 4; l++) {
        const float* vl = vb + (size_t)l * 1024 * 64;
#pragma unroll
        for (int p = 0; p < 8; p++) {
            float wgt = lg[l * 8 + p] * inv;
            float2 ov = __half22float2(off2[l * 8 + p]);
            float fx = (rx + ov.x * (1.f / 32.f)) * 32.f - 0.5f;
            float fy = (ry + ov.y * (1.f / 32.f)) * 32.f - 0.5f;
            float x0f = floorf(fx), y0f = floorf(fy);
            int xi = (int)x0f, yi = (int)y0f;
            float wx = fx - x0f, wy = fy - y0f;
            SAMP(xi,     yi,     wgt * (1.f - wx) * (1.f - wy));
            SAMP(xi + 1, yi,     wgt * wx * (1.f - wy));
            SAMP(xi,     yi + 1, wgt * (1.f - wx) * wy);
            SAMP(xi + 1, yi + 1, wgt * wx * wy);
        }
    }
#undef SAMP
#pragma unroll
    for (int d = 0; d < 8; d++)
        g_attn[((size_t)b * 64 + h * 8 + d) * 4096 + q] = acc[d];
}

// ---------------- fuse + bilinear resize -> padded g_nfr (tf32, zero halo) ----------------
__global__ void k_fuse_resize(int l, int oh, int ow, int PH, int PW4,
                              float hs, size_t nfr_off, int count) {
    int idx = blockIdx.x * 256 + threadIdx.x;
    if (idx >= count) return;
    int px = idx % PW4;
    int t = idx / PW4;
    int py = t % PH; t /= PH;
    int c = t % 320;
    int b = t / 320;
    int gy = py - 1, gx = px - 1;
    float res = 0.f;
    if (gy >= 0 && gy < oh && gx >= 0 && gx < ow) {
        float sy = fmaxf((gy + 0.5f) * hs - 0.5f, 0.f);
        float sx = fmaxf((gx + 0.5f) * hs - 0.5f, 0.f);
        int y0 = (int)sy, x0 = (int)sx;
        float fy = sy - y0, fx = sx - x0;
        int y1 = min(y0 + 1, 31), x1 = min(x0 + 1, 31);
        const float* p;
        if (c < 256)
            p = g_lat + ((size_t)(l * 16 + b) * 256 + c) * 1024;
        else
            p = g_src2 + ((size_t)b * 64 + (c - 256)) * 4096 + l * 1024;
        float v00 = p[y0 * 32 + x0], v01 = p[y0 * 32 + x1];
        float v10 = p[y1 * 32 + x0], v11 = p[y1 * 32 + x1];
        float r0 = v00 * (1.f - fy) + v10 * fy;
        float r1 = v01 * (1.f - fy) + v11 * fy;
        res = tf32f(r0 * (1.f - fx) + r1 * fx);
    }
    g_nfr[nfr_off + (size_t)idx] = res;
}

// ---------------- 3x3 conv 320->256 pad1, TF32 MMA, 64oc, shared-B, 2-stage (R12 proven) ----------------
__global__ __launch_bounds__(256) void k_conv_tc(int l, int oh, int ow, int PW4, int planesz,
                                                 size_t nfr_off,
                                                 const float* __restrict__ cb,
                                                 float* __restrict__ out, size_t out_off)
{
    extern __shared__ __align__(16) float smem[];
    float* Ws = smem;                 // 2 x 4608 floats
    float* Is = smem + 9216;          // 2 x 2880 floats
    int b = blockIdx.z;
    int ocb = blockIdx.y;             // 0..3 -> 64 oc
    int tiles_x = ow >> 4;
    int py0 = (blockIdx.x / tiles_x) << 4;
    int px0 = (blockIdx.x % tiles_x) << 4;
    int tid = threadIdx.x;
    int lane = tid & 31, w = tid >> 5;
    int r0 = w * 2;
    int ohow = oh * ow;
    const float4* wsrc = (const float4*)g_wF
                       + (size_t)l * 184320 + (size_t)ocb * 1152;
    const float* ibase = g_nfr + nfr_off + (size_t)b * 320 * planesz;
    float acc[4][4][4] = {};

    int nops = 0;
    int s_off[3];
    int g_ofs[3];
#pragma unroll
    for (int i = tid; i < 720; i += 256) {
        int kc = i / 90, r2 = i - kc * 90;
        int iy = r2 / 5, s = r2 - iy * 5;
        s_off[nops] = kc * 360 + iy * 20 + s * 4;
        g_ofs[nops] = kc * planesz + (py0 + iy) * PW4 + px0 + s * 4;
        nops++;
    }

#define ISSUE_STAGE(stage, buf) do {                                           \
        const float* chb = ibase + (size_t)((stage) * 8) * planesz;            \
        float* isb_ = Is + (buf) * 2880;                                       \
        for (int j2 = 0; j2 < nops; j2++) cp16(isb_ + s_off[j2], chb + g_ofs[j2]); \
        const float4* wc = wsrc + (size_t)(stage) * 4608;                      \
        float4* wd = (float4*)(Ws + (buf) * 4608);                             \
        _Pragma("unroll")                                                      \
        for (int i2 = 0; i2 < 5; i2++) {                                       \
            int k = tid + i2 * 256;                                            \
            if (k < 1152) cp16(&wd[k], &wc[k]);                                \
        }                                                                      \
        cp_commit(); } while (0)

    ISSUE_STAGE(0, 0);
    ISSUE_STAGE(1, 1);

    for (int c = 0; c < 40; c++) {
        int buf = c & 1;
        if (c < 39) { asm volatile("cp.async.wait_group 1;\n"); }
        else        { asm volatile("cp.async.wait_group 0;\n"); }
        __syncthreads();
        const float* wsA = Ws + buf * 4608 + lane * 4;
        const float* isb = Is + buf * 2880 + (lane & 3) * 360 + (lane >> 2);
#pragma unroll
        for (int tap = 0; tap < 9; tap++) {
            int dy = tap / 3, dx = tap - dy * 3;
            uint4 A0 = *(const uint4*)(wsA + tap * 128);
            uint4 A1 = *(const uint4*)(wsA + 1152 + tap * 128);
            uint4 A2 = *(const uint4*)(wsA + 2304 + tap * 128);
            uint4 A3 = *(const uint4*)(wsA + 3456 + tap * 128);
            const float* ib = isb + (r0 + dy) * 20 + dx;
#pragma unroll
            for (int j = 0; j < 4; j++) {
                const float* bp = ib + (j >> 1) * 20 + ((j & 1) << 3);
                unsigned b0 = __float_as_uint(bp[0]);
                unsigned b1 = __float_as_uint(bp[4 * 360]);
                mma_tf32(acc[0][j], A0, b0, b1);
                mma_tf32(acc[1][j], A1, b0, b1);
                mma_tf32(acc[2][j], A2, b0, b1);
                mma_tf32(acc[3][j], A3, b0, b1);
            }
        }
        __syncthreads();
        if (c + 2 < 40) ISSUE_STAGE(c + 2, buf);
    }
#undef ISSUE_STAGE

    int row = lane >> 2, colp = (lane & 3) << 1;
    int oc0 = ocb * 64;
#pragma unroll
    for (int m = 0; m < 4; m++) {
        int ocA = oc0 + m * 16 + row;
        float bA = cb[l * 256 + ocA];
        float bB = cb[l * 256 + ocA + 8];
        float* outA = out + out_off + (size_t)(b * 256 + ocA) * ohow;
        float* outB = outA + (size_t)8 * ohow;
#pragma unroll
        for (int j = 0; j < 4; j++) {
            int gy = py0 + r0 + (j >> 1);
            int gx = px0 + ((j & 1) << 3) + colp;
            float2 v0 = make_float2(acc[m][j][0] + bA, acc[m][j][1] + bA);
            float2 v1 = make_float2(acc[m][j][2] + bB, acc[m][j][3] + bB);
            *(float2*)(outA + gy * ow + gx) = v0;
            *(float2*)(outB + gy * ow + gx) = v1;
        }
    }
}

// ---------------- launch ----------------
extern "C" void kernel_launch(void* const* d_in, const int* in_sizes, int n_in,
                              void* d_out, int out_size)
{
    const float* x0     = (const float*)d_in[0];
    const float* x1     = (const float*)d_in[1];
    const float* x2     = (const float*)d_in[2];
    const float* x3     = (const float*)d_in[3];
    const float* lat_w  = (const float*)d_in[4];
    const float* lat_b  = (const float*)d_in[5];
    const float* proj_w = (const float*)d_in[6];
    const float* proj_b = (const float*)d_in[7];
    const float* bn_g   = (const float*)d_in[8];
    const float* bn_b   = (const float*)d_in[9];
    const float* bn_m   = (const float*)d_in[10];
    const float* bn_v   = (const float*)d_in[11];
    const float* conv_w = (const float*)d_in[12];
    const float* conv_b = (const float*)d_in[13];
    const float* lemb   = (const float*)d_in[14];
    const float* off_w  = (const float*)d_in[15];
    const float* off_b  = (const float*)d_in[16];
    const float* attw_w = (const float*)d_in[17];
    const float* attw_b = (const float*)d_in[18];
    const float* val_w  = (const float*)d_in[19];
    const float* val_b  = (const float*)d_in[20];
    const float* out_w  = (const float*)d_in[21];
    const float* out_b  = (const float*)d_in[22];
    float* out = (float*)d_out;

    cudaFuncSetAttribute(k_conv_tc, cudaFuncAttributeMaxDynamicSharedMemorySize, 61440);

    k_wtrans<<<11520, 256>>>(conv_w);
    k_prep<<<2672, 256>>>(lat_w, proj_w, off_w, attw_w, val_w, out_w, lemb);
    k_lat_tc<<<dim3(16, 4, 64), 256>>>(x0, x1, x2, x3, lat_b);
    k_proj_tc<<<dim3(16, 1, 64), 256>>>(proj_b, bn_g, bn_b, bn_m, bn_v);
    k_val_tc<<<dim3(1, 64, 16), 256>>>(val_b);
    k_off_tc<<<dim3(20, 64, 16), 256>>>(off_b, attw_b);
    k_sample<<<2048, 256>>>();
    k_out_tc<<<dim3(64, 1, 16), 256>>>(out_b);

    const int    OHS[4]  = {16, 32, 64, 128};
    const int    PW4S[4] = {20, 36, 68, 132};
    const int    PLSZ[4] = {360, 1224, 4488, 17160};
    const size_t NFR[4]  = {0, 1843200, 8110080, 31088640};
    const size_t OUT[4]  = {0, 1048576, 5242880, 22020096};
    for (int l = 0; l < 4; l++) {
        int oh = OHS[l], ow = oh;
        int PH = oh + 2, PW4 = PW4S[l];
        int count = 16 * 320 * PH * PW4;
        float hs = 32.0f / (float)oh;
        k_fuse_resize<<<count / 256, 256>>>(l, oh, ow, PH, PW4, hs, NFR[l], count);
    }
    for (int l = 0; l < 4; l++) {
        int oh = OHS[l], ow = oh;
        dim3 grid((oh / 16) * (ow / 16), 4, 16);
        k_conv_tc<<<grid, 256, 59904>>>(l, oh, ow, PW4S[l], PLSZ[l], NFR[l],
                                        conv_b, out, OUT[l]);
    }
}

// round 17
// speedup vs baseline: 1.0497x; 1.0265x over previous
#include <cuda_runtime.h>
#include <cuda_fp16.h>
#include <math.h>

// ---------------- problem constants ----------------
// B=16, L=4 levels (all 32x32), C=256, EMB=64, Lq=4096, HEADS=8, PTS=8, DH=8
// conv: 320ch -> 256ch, 3x3 pad1 on grids 16/32/64/128

// ---------------- device scratch ----------------
__device__ float g_lat  [16777216];   // [l*16+b][256][1024]
__device__ float g_src  [4194304];    // [b][64][4096]
__device__ float g_pos  [262144];     // [64][4096]
__device__ __half g_valueH[4194304];  // [b][4096][64] value, fp16
__device__ __half g_offH[67108864];   // [b][4096][1024] sampling offsets, fp16
__device__ __half g_attwH[16777216];  // [b][4096][256] attention logits, fp16
__device__ float g_attn [4194304];    // [b][64][4096]
__device__ float g_src2 [4194304];    // [b][64][4096]
__device__ float g_wF   [2949120];    // conv weights tf32 frag order [l][chunk40][mg16][tap9][lane32][4]
__device__ float g_latF [262144];     // lat weights tf32 A-frag [l][kt8 32][mt 16][lane32][4]
__device__ float g_projF[65536];      // proj weights tf32 A-frag [l][kt8 32][mt 4][lane32][4]
__device__ float g_outF [4096];       // out weights tf32 A-frag [kt8 8][mt 4][lane32][4]
__device__ float g_oaF  [90112];      // off(128)+attw(32)+val(8)+spare(8) nt=176 tf32 B-frag [kt8 8][nt 176][lane32][2]
__device__ float g_nfr  [118947840];  // padded resized nf (tf32): [b][320][oh+2][ow+4]

__device__ __forceinline__ unsigned f2tf32(float v) {
    unsigned o;
    asm("cvt.rna.tf32.f32 %0, %1;" : "=r"(o) : "f"(v));
    return o;
}
__device__ __forceinline__ float tf32f(float v) { return __uint_as_float(f2tf32(v)); }

__device__ __forceinline__ void mma_tf32(float* c, uint4 a, unsigned b0, unsigned b1) {
    asm volatile("mma.sync.aligned.m16n8k8.row.col.f32.tf32.tf32.f32 "
        "{%0,%1,%2,%3}, {%4,%5,%6,%7}, {%8,%9}, {%0,%1,%2,%3};\n"
        : "+f"(c[0]), "+f"(c[1]), "+f"(c[2]), "+f"(c[3])
        : "r"(a.x), "r"(a.y), "r"(a.z), "r"(a.w), "r"(b0), "r"(b1));
}
__device__ __forceinline__ void cp16(void* dst, const void* src) {
    unsigned d = (unsigned)__cvta_generic_to_shared(dst);
    asm volatile("cp.async.cg.shared.global [%0], [%1], 16;\n" :: "r"(d), "l"(src));
}
__device__ __forceinline__ void cp_commit() { asm volatile("cp.async.commit_group;\n"); }

// ---------------- conv weight repack: fragment-order + tf32 ----------------
__global__ void k_wtrans(const float* __restrict__ w) {
    int idx = blockIdx.x * 256 + threadIdx.x;
    if (idx >= 4 * 40 * 16 * 9 * 32 * 4) return;
    int r    = idx & 3;
    int lane = (idx >> 2) & 31;
    int tap  = (idx >> 7) % 9;
    int mg   = (idx / 1152) & 15;
    int chunk= (idx / 18432) % 40;
    int l    = idx / 737280;
    int oc   = mg * 16 + (lane >> 2) + 8 * (r & 1);
    int ic   = chunk * 8 + (lane & 3) + 4 * (r >> 1);
    float v = w[(((size_t)(l * 256 + oc)) * 320 + ic) * 9 + tap];
    g_wF[idx] = tf32f(v);
}

// ---------------- merged prep: lat/proj/out A packs, off+attw+val B pack, pos ----------------
__global__ void k_prep(const float* __restrict__ lat_w, const float* __restrict__ proj_w,
                       const float* __restrict__ off_w, const float* __restrict__ attw_w,
                       const float* __restrict__ val_w, const float* __restrict__ out_w,
                       const float* __restrict__ lemb) {
    int idx = blockIdx.x * 256 + threadIdx.x;
    if (idx < 262144) {                 // lateral A-frag pack
        int r = idx & 3, lane = (idx >> 2) & 31, mt = (idx >> 7) & 15;
        int kt8 = (idx >> 11) & 31, l = idx >> 16;
        int row = mt * 16 + (lane >> 2) + 8 * (r & 1);
        int k   = kt8 * 8 + (lane & 3) + 4 * (r >> 1);
        g_latF[idx] = tf32f(lat_w[(size_t)l * 65536 + row * 256 + k]);
    } else if (idx < 327680) {          // proj A-frag pack
        int id = idx - 262144;
        int r = id & 3, lane = (id >> 2) & 31, mt = (id >> 7) & 3;
        int kt8 = (id >> 9) & 31, l = id >> 14;
        int row = mt * 16 + (lane >> 2) + 8 * (r & 1);
        int k   = kt8 * 8 + (lane & 3) + 4 * (r >> 1);
        g_projF[id] = tf32f(proj_w[(size_t)l * 16384 + row * 256 + k]);
    } else if (idx < 417792) {          // off+attw+val B-frag pack (nt 0..175)
        int id = idx - 327680;
        int i = id & 1, lane = (id >> 1) & 31, nt = (id >> 6) % 176, kt8 = id / 11264;
        int n = nt * 8 + (lane >> 2);
        int k = kt8 * 8 + (lane & 3) + 4 * i;
        float v;
        if (n < 1024)       v = off_w[n * 64 + k];
        else if (n < 1280)  v = attw_w[(n - 1024) * 64 + k];
        else if (n < 1344)  v = val_w[(n - 1280) * 64 + k];
        else                v = 0.f;
        g_oaF[id] = tf32f(v);
    } else if (idx < 679936) {          // sine pos + level embed
        int id = idx - 417792;
        int e = id >> 12, q = id & 4095;
        int l = q >> 10, hw = q & 1023, y = hw >> 5, x = hw & 31;
        int e2 = (e < 32) ? e : (e - 32);
        int n  = (e < 32) ? (y + 1) : (x + 1);
        int j  = e2 >> 1;
        float t = powf(10000.f, (float)j * (1.f / 16.f));
        float p = (float)n / t;
        float v = (e2 & 1) ? cosf(p) : sinf(p);
        g_pos[id] = v + lemb[l * 64 + e];
    } else if (idx < 684032) {          // out-proj A-frag pack (4096 entries)
        int id = idx - 679936;
        int r = id & 3, lane = (id >> 2) & 31, mt = (id >> 7) & 3, kt8 = id >> 9;
        int row = mt * 16 + (lane >> 2) + 8 * (r & 1);
        int k   = kt8 * 8 + (lane & 3) + 4 * (r >> 1);
        g_outF[id] = tf32f(out_w[row * 64 + k]);
    }
}

// ---------------- lateral 1x1 conv via TF32 MMA, register-prefetch pipelined ----------------
__global__ __launch_bounds__(256) void k_lat_tc(
    const float* __restrict__ x0, const float* __restrict__ x1,
    const float* __restrict__ x2, const float* __restrict__ x3,
    const float* __restrict__ bias)
{
    __shared__ __align__(16) float AsF[2048];
    __shared__ __align__(16) float Bs[32 * 68];
    int lb = blockIdx.z, l = lb >> 4, b = lb & 15;
    const float* X = (l == 0 ? x0 : l == 1 ? x1 : l == 2 ? x2 : x3) + (size_t)b * 262144;
    const float* AF = g_latF + (size_t)l * 65536;
    int m0 = blockIdx.y * 64, n0 = blockIdx.x * 64;
    int tid = threadIdx.x, lane = tid & 31, w = tid >> 5;
    int warp_m = w >> 2, warp_n = w & 3;
    int n_w = warp_n * 16;
    float acc[2][2][4] = {};
    float4 aReg[2], bReg[2];

#define LAT_LOAD(cc) do {                                                           \
        int k0_ = (cc) * 32;                                                        \
        _Pragma("unroll")                                                           \
        for (int i = 0; i < 2; i++) {                                               \
            int id = tid + i * 256;                                                 \
            aReg[i] = ((const float4*)AF)[((k0_ >> 3) + (id >> 7)) * 512            \
                                          + (m0 >> 4) * 32 + (id & 127)];           \
            int k = id >> 4, n4 = (id & 15) << 2;                                   \
            bReg[i] = *(const float4*)&X[(size_t)(k0_ + k) * 1024 + n0 + n4];       \
        } } while (0)

    LAT_LOAD(0);
    for (int c = 0; c < 8; c++) {
        __syncthreads();
#pragma unroll
        for (int i = 0; i < 2; i++) {
            int id = tid + i * 256;
            ((float4*)AsF)[id] = aReg[i];
            float4 v = bReg[i];
            v.x = tf32f(v.x); v.y = tf32f(v.y); v.z = tf32f(v.z); v.w = tf32f(v.w);
            int k = id >> 4, n4 = (id & 15) << 2;
            *(float4*)&Bs[k * 68 + n4] = v;
        }
        if (c + 1 < 8) LAT_LOAD(c + 1);
        __syncthreads();
#pragma unroll
        for (int kk = 0; kk < 4; kk++) {
            uint4 A0 = *(const uint4*)&AsF[(kk * 4 + warp_m * 2 + 0) * 128 + lane * 4];
            uint4 A1 = *(const uint4*)&AsF[(kk * 4 + warp_m * 2 + 1) * 128 + lane * 4];
#pragma unroll
            for (int j = 0; j < 2; j++) {
                const float* bp = &Bs[(kk * 8 + (lane & 3)) * 68 + n_w + j * 8 + (lane >> 2)];
                unsigned b0 = __float_as_uint(bp[0]);
                unsigned b1 = __float_as_uint(bp[4 * 68]);
                mma_tf32(acc[0][j], A0, b0, b1);
                mma_tf32(acc[1][j], A1, b0, b1);
            }
        }
    }
#undef LAT_LOAD
    float* O = g_lat + (size_t)lb * 262144;
    int row_l = lane >> 2, colp = (lane & 3) << 1;
#pragma unroll
    for (int h = 0; h < 2; h++)
#pragma unroll
        for (int j = 0; j < 2; j++) {
            int row = m0 + warp_m * 32 + h * 16 + row_l;
            int col = n0 + n_w + j * 8 + colp;
            float b0v = bias[l * 256 + row], b1v = bias[l * 256 + row + 8];
            *(float2*)&O[(size_t)row * 1024 + col] =
                make_float2(acc[h][j][0] + b0v, acc[h][j][1] + b0v);
            *(float2*)&O[(size_t)(row + 8) * 1024 + col] =
                make_float2(acc[h][j][2] + b1v, acc[h][j][3] + b1v);
        }
}

// ---------------- proj (256->64) via TF32 MMA + BN + ReLU, register-prefetch ----------------
__global__ __launch_bounds__(256) void k_proj_tc(
    const float* __restrict__ bias,
    const float* __restrict__ bng, const float* __restrict__ bnb,
    const float* __restrict__ bnm, const float* __restrict__ bnv)
{
    __shared__ __align__(16) float AsF[2048];
    __shared__ __align__(16) float Bs[32 * 68];
    int lb = blockIdx.z, l = lb >> 4, b = lb & 15;
    const float* X = g_lat + (size_t)lb * 262144;
    const float* AF = g_projF + (size_t)l * 16384;
    int n0 = blockIdx.x * 64;
    int tid = threadIdx.x, lane = tid & 31, w = tid >> 5;
    int warp_m = w >> 2, warp_n = w & 3;
    int n_w = warp_n * 16;
    float acc[2][2][4] = {};
    float4 aReg[2], bReg[2];

#define PROJ_LOAD(cc) do {                                                          \
        int k0_ = (cc) * 32;                                                        \
        _Pragma("unroll")                                                           \
        for (int i = 0; i < 2; i++) {                                               \
            int id = tid + i * 256;                                                 \
            aReg[i] = ((const float4*)AF)[(((cc) * 4 + (id >> 7)) * 128) + (id & 127)]; \
            int k = id >> 4, n4 = (id & 15) << 2;                                   \
            bReg[i] = *(const float4*)&X[(size_t)(k0_ + k) * 1024 + n0 + n4];       \
        } } while (0)

    PROJ_LOAD(0);
    for (int c = 0; c < 8; c++) {
        __syncthreads();
#pragma unroll
        for (int i = 0; i < 2; i++) {
            int id = tid + i * 256;
            ((float4*)AsF)[id] = aReg[i];
            float4 v = bReg[i];
            v.x = tf32f(v.x); v.y = tf32f(v.y); v.z = tf32f(v.z); v.w = tf32f(v.w);
            int k = id >> 4, n4 = (id & 15) << 2;
            *(float4*)&Bs[k * 68 + n4] = v;
        }
        if (c + 1 < 8) PROJ_LOAD(c + 1);
        __syncthreads();
#pragma unroll
        for (int kk = 0; kk < 4; kk++) {
            uint4 A0 = *(const uint4*)&AsF[(kk * 4 + warp_m * 2 + 0) * 128 + lane * 4];
            uint4 A1 = *(const uint4*)&AsF[(kk * 4 + warp_m * 2 + 1) * 128 + lane * 4];
#pragma unroll
            for (int j = 0; j < 2; j++) {
                const float* bp = &Bs[(kk * 8 + (lane & 3)) * 68 + n_w + j * 8 + (lane >> 2)];
                unsigned b0 = __float_as_uint(bp[0]);
                unsigned b1 = __float_as_uint(bp[4 * 68]);
                mma_tf32(acc[0][j], A0, b0, b1);
                mma_tf32(acc[1][j], A1, b0, b1);
            }
        }
    }
#undef PROJ_LOAD
    int row_l = lane >> 2, colp = (lane & 3) << 1;
#pragma unroll
    for (int h = 0; h < 2; h++) {
        int m = warp_m * 32 + h * 16 + row_l;
        float sc0 = bng[l * 64 + m] * rsqrtf(bnv[l * 64 + m] + 1e-5f);
        float sh0 = bnb[l * 64 + m] - bnm[l * 64 + m] * sc0 + bias[l * 64 + m] * sc0;
        float sc1 = bng[l * 64 + m + 8] * rsqrtf(bnv[l * 64 + m + 8] + 1e-5f);
        float sh1 = bnb[l * 64 + m + 8] - bnm[l * 64 + m + 8] * sc1 + bias[l * 64 + m + 8] * sc1;
#pragma unroll
        for (int j = 0; j < 2; j++) {
            int col = n0 + n_w + j * 8 + colp;
            float* p0 = &g_src[((size_t)b * 64 + m) * 4096 + l * 1024 + col];
            float* p1 = &g_src[((size_t)b * 64 + m + 8) * 4096 + l * 1024 + col];
            *(float2*)p0 = make_float2(fmaxf(acc[h][j][0] * sc0 + sh0, 0.f),
                                       fmaxf(acc[h][j][1] * sc0 + sh0, 0.f));
            *(float2*)p1 = make_float2(fmaxf(acc[h][j][2] * sc1 + sh1, 0.f),
                                       fmaxf(acc[h][j][3] * sc1 + sh1, 0.f));
        }
    }
}

// ---------------- off(1024,fp16)+attw(256,fp16) GEMM via TF32 MMA: M=q4096, N=1280, K=64 ----------------
__global__ __launch_bounds__(256) void k_off_tc(const float* __restrict__ off_b,
                                                const float* __restrict__ attw_b)
{
    __shared__ __align__(16) float As[64 * 68];
    __shared__ __align__(16) float BsF[4096];
    int b = blockIdx.z;
    int q0 = blockIdx.y * 64, n0 = blockIdx.x * 64;
    int tid = threadIdx.x, lane = tid & 31, w = tid >> 5;
    int warp_m = w >> 2, warp_n = w & 3;
    const float* S = g_src + (size_t)b * 262144;
#pragma unroll
    for (int i = 0; i < 4; i++) {
        int id = tid + i * 256;
        int k = id >> 4, q4 = (id & 15) << 2;
        float4 v = *(const float4*)&S[(size_t)k * 4096 + q0 + q4];
        float4 p = *(const float4*)&g_pos[(size_t)k * 4096 + q0 + q4];
        v.x = tf32f(v.x + p.x); v.y = tf32f(v.y + p.y);
        v.z = tf32f(v.z + p.z); v.w = tf32f(v.w + p.w);
        *(float4*)&As[k * 68 + q4] = v;
    }
#pragma unroll
    for (int i = 0; i < 4; i++) {
        int id = tid + i * 256;
        int kt8 = id >> 7, rem = id & 127;
        ((float4*)BsF)[id] = ((const float4*)g_oaF)[(kt8 * 176 + (n0 >> 3)) * 16 + rem];
    }
    __syncthreads();
    float acc[2][2][4] = {};
#pragma unroll
    for (int kk8 = 0; kk8 < 8; kk8++) {
        uint4 A[2];
#pragma unroll
        for (int h = 0; h < 2; h++) {
            const float* ap = &As[(kk8 * 8 + (lane & 3)) * 68 + warp_m * 32 + h * 16 + (lane >> 2)];
            A[h].x = __float_as_uint(ap[0]);
            A[h].y = __float_as_uint(ap[8]);
            A[h].z = __float_as_uint(ap[4 * 68]);
            A[h].w = __float_as_uint(ap[4 * 68 + 8]);
        }
#pragma unroll
        for (int j = 0; j < 2; j++) {
            float2 bv = *(const float2*)&BsF[(kk8 * 8 + warp_n * 2 + j) * 64 + lane * 2];
            unsigned b0 = __float_as_uint(bv.x), b1 = __float_as_uint(bv.y);
            mma_tf32(acc[0][j], A[0], b0, b1);
            mma_tf32(acc[1][j], A[1], b0, b1);
        }
    }
    int row_l = lane >> 2, colp = (lane & 3) << 1;
    bool is_off = (n0 < 1024);
#pragma unroll
    for (int h = 0; h < 2; h++)
#pragma unroll
        for (int j = 0; j < 2; j++) {
            int q = q0 + warp_m * 32 + h * 16 + row_l;
            int col = n0 + warp_n * 16 + j * 8 + colp;
            if (is_off) {
                float bb0 = off_b[col], bb1 = off_b[col + 1];
                __half* op = g_offH + ((size_t)b * 4096 + q) * 1024 + col;
                *(__half2*)op = __floats2half2_rn(acc[h][j][0] + bb0, acc[h][j][1] + bb1);
                *(__half2*)(op + 8 * 1024) = __floats2half2_rn(acc[h][j][2] + bb0, acc[h][j][3] + bb1);
            } else {
                int ca = col - 1024;
                float bb0 = attw_b[ca], bb1 = attw_b[ca + 1];
                __half* op = g_attwH + ((size_t)b * 4096 + q) * 256 + ca;
                *(__half2*)op = __floats2half2_rn(acc[h][j][0] + bb0, acc[h][j][1] + bb1);
                *(__half2*)(op + 8 * 256) = __floats2half2_rn(acc[h][j][2] + bb0, acc[h][j][3] + bb1);
            }
        }
}

// ---------------- value GEMM via TF32 MMA: M=q4096, N=64, K=64 -> g_valueH [b][q][64] fp16 ----------------
__global__ __launch_bounds__(256) void k_val_tc(const float* __restrict__ bias)
{
    __shared__ __align__(16) float As[64 * 68];
    __shared__ __align__(16) float BsF[4096];
    int b = blockIdx.z;
    int q0 = blockIdx.y * 64;
    int tid = threadIdx.x, lane = tid & 31, w = tid >> 5;
    int warp_m = w >> 2, warp_n = w & 3;
    const float* S = g_src + (size_t)b * 262144;
#pragma unroll
    for (int i = 0; i < 4; i++) {
        int id = tid + i * 256;
        int k = id >> 4, q4 = (id & 15) << 2;
        float4 v = *(const float4*)&S[(size_t)k * 4096 + q0 + q4];
        v.x = tf32f(v.x); v.y = tf32f(v.y); v.z = tf32f(v.z); v.w = tf32f(v.w);
        *(float4*)&As[k * 68 + q4] = v;
    }
#pragma unroll
    for (int i = 0; i < 4; i++) {
        int id = tid + i * 256;
        int kt8 = id >> 7, rem = id & 127;
        ((float4*)BsF)[id] = ((const float4*)g_oaF)[(kt8 * 176 + 160 + (rem >> 4)) * 16 + (rem & 15)];
    }
    __syncthreads();
    float acc[2][2][4] = {};
#pragma unroll
    for (int kk8 = 0; kk8 < 8; kk8++) {
        uint4 A[2];
#pragma unroll
        for (int h = 0; h < 2; h++) {
            const float* ap = &As[(kk8 * 8 + (lane & 3)) * 68 + warp_m * 32 + h * 16 + (lane >> 2)];
            A[h].x = __float_as_uint(ap[0]);
            A[h].y = __float_as_uint(ap[8]);
            A[h].z = __float_as_uint(ap[4 * 68]);
            A[h].w = __float_as_uint(ap[4 * 68 + 8]);
        }
#pragma unroll
        for (int j = 0; j < 2; j++) {
            float2 bv = *(const float2*)&BsF[(kk8 * 8 + warp_n * 2 + j) * 64 + lane * 2];
            unsigned b0 = __float_as_uint(bv.x), b1 = __float_as_uint(bv.y);
            mma_tf32(acc[0][j], A[0], b0, b1);
            mma_tf32(acc[1][j], A[1], b0, b1);
        }
    }
    int row_l = lane >> 2, colp = (lane & 3) << 1;
#pragma unroll
    for (int h = 0; h < 2; h++)
#pragma unroll
        for (int j = 0; j < 2; j++) {
            int q = q0 + warp_m * 32 + h * 16 + row_l;
            int col = warp_n * 16 + j * 8 + colp;
            float bb0 = bias[col], bb1 = bias[col + 1];
            __half* op = g_valueH + ((size_t)b * 4096 + q) * 64 + col;
            *(__half2*)op = __floats2half2_rn(acc[h][j][0] + bb0, acc[h][j][1] + bb1);
            *(__half2*)(op + 8 * 64) = __floats2half2_rn(acc[h][j][2] + bb0, acc[h][j][3] + bb1);
        }
}

// ---------------- out-proj via TF32 MMA (lat-style): M=64, K=64, N=4096 per b ----------------
__global__ __launch_bounds__(256) void k_out_tc(const float* __restrict__ bias)
{
    __shared__ __align__(16) float AsF[2048];
    __shared__ __align__(16) float Bs[32 * 68];
    int b = blockIdx.z;
    const float* X = g_attn + (size_t)b * 262144;
    int n0 = blockIdx.x * 64;
    int tid = threadIdx.x, lane = tid & 31, w = tid >> 5;
    int warp_m = w >> 2, warp_n = w & 3;
    int n_w = warp_n * 16;
    float acc[2][2][4] = {};
    for (int c = 0; c < 2; c++) {
        int k0 = c * 32;
        __syncthreads();
#pragma unroll
        for (int i = 0; i < 2; i++) {
            int id = tid + i * 256;
            int kt = id >> 7, rem = id & 127;
            ((float4*)AsF)[id] = ((const float4*)g_outF)[((k0 >> 3) + kt) * 128 + rem];
        }
#pragma unroll
        for (int i = 0; i < 2; i++) {
            int id = tid + i * 256;
            int k = id >> 4, n4 = (id & 15) << 2;
            float4 v = *(const float4*)&X[(size_t)(k0 + k) * 4096 + n0 + n4];
            v.x = tf32f(v.x); v.y = tf32f(v.y); v.z = tf32f(v.z); v.w = tf32f(v.w);
            *(float4*)&Bs[k * 68 + n4] = v;
        }
        __syncthreads();
#pragma unroll
        for (int kk = 0; kk < 4; kk++) {
            uint4 A0 = *(const uint4*)&AsF[(kk * 4 + warp_m * 2 + 0) * 128 + lane * 4];
            uint4 A1 = *(const uint4*)&AsF[(kk * 4 + warp_m * 2 + 1) * 128 + lane * 4];
#pragma unroll
            for (int j = 0; j < 2; j++) {
                const float* bp = &Bs[(kk * 8 + (lane & 3)) * 68 + n_w + j * 8 + (lane >> 2)];
                unsigned b0 = __float_as_uint(bp[0]);
                unsigned b1 = __float_as_uint(bp[4 * 68]);
                mma_tf32(acc[0][j], A0, b0, b1);
                mma_tf32(acc[1][j], A1, b0, b1);
            }
        }
    }
    float* O = g_src2 + (size_t)b * 262144;
    int row_l = lane >> 2, colp = (lane & 3) << 1;
#pragma unroll
    for (int h = 0; h < 2; h++)
#pragma unroll
        for (int j = 0; j < 2; j++) {
            int row = warp_m * 32 + h * 16 + row_l;
            int col = n0 + n_w + j * 8 + colp;
            float b0v = bias[row], b1v = bias[row + 8];
            *(float2*)&O[(size_t)row * 4096 + col] =
                make_float2(acc[h][j][0] + b0v, acc[h][j][1] + b0v);
            *(float2*)&O[(size_t)(row + 8) * 4096 + col] =
                make_float2(acc[h][j][2] + b1v, acc[h][j][3] + b1v);
        }
}

// ---------------- deformable attention sampling (fp16 offsets/logits/values) ----------------
__global__ void k_sample() {
    int idx = blockIdx.x * 256 + threadIdx.x;
    if (idx >= 16 * 4096 * 8) return;
    int h = idx & 7, q = (idx >> 3) & 4095, b = idx >> 15;
    const __half2* aw2 = (const __half2*)(g_attwH + (size_t)(b * 4096 + q) * 256 + h * 32);
    const __half2* off2 = (const __half2*)(g_offH + (size_t)(b * 4096 + q) * 1024 + h * 64);
    float lg[32];
#pragma unroll
    for (int j = 0; j < 16; j++) {
        float2 f = __half22float2(aw2[j]);
        lg[2 * j] = f.x; lg[2 * j + 1] = f.y;
    }
    float mx = lg[0];
#pragma unroll
    for (int j = 1; j < 32; j++) mx = fmaxf(mx, lg[j]);
    float s = 0.f;
#pragma unroll
    for (int j = 0; j < 32; j++) { lg[j] = __expf(lg[j] - mx); s += lg[j]; }
    float inv = 1.f / s;
    int y = (q & 1023) >> 5, x = q & 31;
    float rx = (x + 0.5f) * (1.f / 32.f), ry = (y + 0.5f) * (1.f / 32.f);
    float acc[8] = {0, 0, 0, 0, 0, 0, 0, 0};
    const __half* vb = g_valueH + (size_t)b * 4096 * 64 + h * 8;

#define SAMP(XX, YY, WW2) do { int xx = (XX), yy = (YY);                            \
        if (xx >= 0 && xx < 32 && yy >= 0 && yy < 32) {                             \
            uint4 u = *(const uint4*)(vl + (size_t)(yy * 32 + xx) * 64);            \
            float2 a0 = __half22float2(*(__half2*)&u.x);                            \
            float2 a1 = __half22float2(*(__half2*)&u.y);                            \
            float2 a2 = __half22float2(*(__half2*)&u.z);                            \
            float2 a3 = __half22float2(*(__half2*)&u.w);                            \
            float wv = (WW2);                                                       \
            acc[0] += wv * a0.x; acc[1] += wv * a0.y; acc[2] += wv * a1.x; acc[3] += wv * a1.y; \
            acc[4] += wv * a2.x; acc[5] += wv * a2.y; acc[6] += wv * a3.x; acc[7] += wv * a3.y; } } while (0)

#pragma unroll
    for (int l = 0; l < 4; l++) {
        const __half* vl = vb + (size_t)l * 1024 * 64;
#pragma unroll
        for (int p = 0; p < 8; p++) {
            float wgt = lg[l * 8 + p] * inv;
            float2 ov = __half22float2(off2[l * 8 + p]);
            float fx = (rx + ov.x * (1.f / 32.f)) * 32.f - 0.5f;
            float fy = (ry + ov.y * (1.f / 32.f)) * 32.f - 0.5f;
            float x0f = floorf(fx), y0f = floorf(fy);
            int xi = (int)x0f, yi = (int)y0f;
            float wx = fx - x0f, wy = fy - y0f;
            SAMP(xi,     yi,     wgt * (1.f - wx) * (1.f - wy));
            SAMP(xi + 1, yi,     wgt * wx * (1.f - wy));
            SAMP(xi,     yi + 1, wgt * (1.f - wx) * wy);
            SAMP(xi + 1, yi + 1, wgt * wx * wy);
        }
    }
#undef SAMP
#pragma unroll
    for (int d = 0; d < 8; d++)
        g_attn[((size_t)b * 64 + h * 8 + d) * 4096 + q] = acc[d];
}

// ---------------- fuse + bilinear resize -> padded g_nfr (tf32, zero halo) ----------------
__global__ void k_fuse_resize(int l, int oh, int ow, int PH, int PW4,
                              float hs, size_t nfr_off, int count) {
    int idx = blockIdx.x * 256 + threadIdx.x;
    if (idx >= count) return;
    int px = idx % PW4;
    int t = idx / PW4;
    int py = t % PH; t /= PH;
    int c = t % 320;
    int b = t / 320;
    int gy = py - 1, gx = px - 1;
    float res = 0.f;
    if (gy >= 0 && gy < oh && gx >= 0 && gx < ow) {
        float sy = fmaxf((gy + 0.5f) * hs - 0.5f, 0.f);
        float sx = fmaxf((gx + 0.5f) * hs - 0.5f, 0.f);
        int y0 = (int)sy, x0 = (int)sx;
        float fy = sy - y0, fx = sx - x0;
        int y1 = min(y0 + 1, 31), x1 = min(x0 + 1, 31);
        const float* p;
        if (c < 256)
            p = g_lat + ((size_t)(l * 16 + b) * 256 + c) * 1024;
        else
            p = g_src2 + ((size_t)b * 64 + (c - 256)) * 4096 + l * 1024;
        float v00 = p[y0 * 32 + x0], v01 = p[y0 * 32 + x1];
        float v10 = p[y1 * 32 + x0], v11 = p[y1 * 32 + x1];
        float r0 = v00 * (1.f - fy) + v10 * fy;
        float r1 = v01 * (1.f - fy) + v11 * fy;
        res = tf32f(r0 * (1.f - fx) + r1 * fx);
    }
    g_nfr[nfr_off + (size_t)idx] = res;
}

// ---------------- 3x3 conv 320->256 pad1, TF32 MMA, 64oc, shared-B, 2-stage (R12 proven) ----------------
__global__ __launch_bounds__(256) void k_conv_tc(int l, int oh, int ow, int PW4, int planesz,
                                                 size_t nfr_off,
                                                 const float* __restrict__ cb,
                                                 float* __restrict__ out, size_t out_off)
{
    extern __shared__ __align__(16) float smem[];
    float* Ws = smem;                 // 2 x 4608 floats
    float* Is = smem + 9216;          // 2 x 2880 floats
    int b = blockIdx.z;
    int ocb = blockIdx.y;             // 0..3 -> 64 oc
    int tiles_x = ow >> 4;
    int py0 = (blockIdx.x / tiles_x) << 4;
    int px0 = (blockIdx.x % tiles_x) << 4;
    int tid = threadIdx.x;
    int lane = tid & 31, w = tid >> 5;
    int r0 = w * 2;
    int ohow = oh * ow;
    const float4* wsrc = (const float4*)g_wF
                       + (size_t)l * 184320 + (size_t)ocb * 1152;
    const float* ibase = g_nfr + nfr_off + (size_t)b * 320 * planesz;
    float acc[4][4][4] = {};

    int nops = 0;
    int s_off[3];
    int g_ofs[3];
#pragma unroll
    for (int i = tid; i < 720; i += 256) {
        int kc = i / 90, r2 = i - kc * 90;
        int iy = r2 / 5, s = r2 - iy * 5;
        s_off[nops] = kc * 360 + iy * 20 + s * 4;
        g_ofs[nops] = kc * planesz + (py0 + iy) * PW4 + px0 + s * 4;
        nops++;
    }

#define ISSUE_STAGE(stage, buf) do {                                           \
        const float* chb = ibase + (size_t)((stage) * 8) * planesz;            \
        float* isb_ = Is + (buf) * 2880;                                       \
        for (int j2 = 0; j2 < nops; j2++) cp16(isb_ + s_off[j2], chb + g_ofs[j2]); \
        const float4* wc = wsrc + (size_t)(stage) * 4608;                      \
        float4* wd = (float4*)(Ws + (buf) * 4608);                             \
        _Pragma("unroll")                                                      \
        for (int i2 = 0; i2 < 5; i2++) {                                       \
            int k = tid + i2 * 256;                                            \
            if (k < 1152) cp16(&wd[k], &wc[k]);                                \
        }                                                                      \
        cp_commit(); } while (0)

    ISSUE_STAGE(0, 0);
    ISSUE_STAGE(1, 1);

    for (int c = 0; c < 40; c++) {
        int buf = c & 1;
        if (c < 39) { asm volatile("cp.async.wait_group 1;\n"); }
        else        { asm volatile("cp.async.wait_group 0;\n"); }
        __syncthreads();
        const float* wsA = Ws + buf * 4608 + lane * 4;
        const float* isb = Is + buf * 2880 + (lane & 3) * 360 + (lane >> 2);
#pragma unroll
        for (int tap = 0; tap < 9; tap++) {
            int dy = tap / 3, dx = tap - dy * 3;
            uint4 A0 = *(const uint4*)(wsA + tap * 128);
            uint4 A1 = *(const uint4*)(wsA + 1152 + tap * 128);
            uint4 A2 = *(const uint4*)(wsA + 2304 + tap * 128);
            uint4 A3 = *(const uint4*)(wsA + 3456 + tap * 128);
            const float* ib = isb + (r0 + dy) * 20 + dx;
#pragma unroll
            for (int j = 0; j < 4; j++) {
                const float* bp = ib + (j >> 1) * 20 + ((j & 1) << 3);
                unsigned b0 = __float_as_uint(bp[0]);
                unsigned b1 = __float_as_uint(bp[4 * 360]);
                mma_tf32(acc[0][j], A0, b0, b1);
                mma_tf32(acc[1][j], A1, b0, b1);
                mma_tf32(acc[2][j], A2, b0, b1);
                mma_tf32(acc[3][j], A3, b0, b1);
            }
        }
        __syncthreads();
        if (c + 2 < 40) ISSUE_STAGE(c + 2, buf);
    }
#undef ISSUE_STAGE

    int row = lane >> 2, colp = (lane & 3) << 1;
    int oc0 = ocb * 64;
#pragma unroll
    for (int m = 0; m < 4; m++) {
        int ocA = oc0 + m * 16 + row;
        float bA = cb[l * 256 + ocA];
        float bB = cb[l * 256 + ocA + 8];
        float* outA = out + out_off + (size_t)(b * 256 + ocA) * ohow;
        float* outB = outA + (size_t)8 * ohow;
#pragma unroll
        for (int j = 0; j < 4; j++) {
            int gy = py0 + r0 + (j >> 1);
            int gx = px0 + ((j & 1) << 3) + colp;
            float2 v0 = make_float2(acc[m][j][0] + bA, acc[m][j][1] + bA);
            float2 v1 = make_float2(acc[m][j][2] + bB, acc[m][j][3] + bB);
            *(float2*)(outA + gy * ow + gx) = v0;
            *(float2*)(outB + gy * ow + gx) = v1;
        }
    }
}

// ---------------- launch ----------------
extern "C" void kernel_launch(void* const* d_in, const int* in_sizes, int n_in,
                              void* d_out, int out_size)
{
    const float* x0     = (const float*)d_in[0];
    const float* x1     = (const float*)d_in[1];
    const float* x2     = (const float*)d_in[2];
    const float* x3     = (const float*)d_in[3];
    const float* lat_w  = (const float*)d_in[4];
    const float* lat_b  = (const float*)d_in[5];
    const float* proj_w = (const float*)d_in[6];
    const float* proj_b = (const float*)d_in[7];
    const float* bn_g   = (const float*)d_in[8];
    const float* bn_b   = (const float*)d_in[9];
    const float* bn_m   = (const float*)d_in[10];
    const float* bn_v   = (const float*)d_in[11];
    const float* conv_w = (const float*)d_in[12];
    const float* conv_b = (const float*)d_in[13];
    const float* lemb   = (const float*)d_in[14];
    const float* off_w  = (const float*)d_in[15];
    const float* off_b  = (const float*)d_in[16];
    const float* attw_w = (const float*)d_in[17];
    const float* attw_b = (const float*)d_in[18];
    const float* val_w  = (const float*)d_in[19];
    const float* val_b  = (const float*)d_in[20];
    const float* out_w  = (const float*)d_in[21];
    const float* out_b  = (const float*)d_in[22];
    float* out = (float*)d_out;

    cudaFuncSetAttribute(k_conv_tc, cudaFuncAttributeMaxDynamicSharedMemorySize, 61440);

    k_wtrans<<<11520, 256>>>(conv_w);
    k_prep<<<2672, 256>>>(lat_w, proj_w, off_w, attw_w, val_w, out_w, lemb);
    k_lat_tc<<<dim3(16, 4, 64), 256>>>(x0, x1, x2, x3, lat_b);
    k_proj_tc<<<dim3(16, 1, 64), 256>>>(proj_b, bn_g, bn_b, bn_m, bn_v);
    k_val_tc<<<dim3(1, 64, 16), 256>>>(val_b);
    k_off_tc<<<dim3(20, 64, 16), 256>>>(off_b, attw_b);
    k_sample<<<2048, 256>>>();
    k_out_tc<<<dim3(64, 1, 16), 256>>>(out_b);

    const int    OHS[4]  = {16, 32, 64, 128};
    const int    PW4S[4] = {20, 36, 68, 132};
    const int    PLSZ[4] = {360, 1224, 4488, 17160};
    const size_t NFR[4]  = {0, 1843200, 8110080, 31088640};
    const size_t OUT[4]  = {0, 1048576, 5242880, 22020096};
    for (int l = 0; l < 4; l++) {
        int oh = OHS[l], ow = oh;
        int PH = oh + 2, PW4 = PW4S[l];
        int count = 16 * 320 * PH * PW4;
        float hs = 32.0f / (float)oh;
        k_fuse_resize<<<count / 256, 256>>>(l, oh, ow, PH, PW4, hs, NFR[l], count);
    }
    for (int l = 0; l < 4; l++) {
        int oh = OHS[l], ow = oh;
        dim3 grid((oh / 16) * (ow / 16), 4, 16);
        k_conv_tc<<<grid, 256, 59904>>>(l, oh, ow, PW4S[l], PLSZ[l], NFR[l],
                                        conv_b, out, OUT[l]);
    }
}